// round 4
// baseline (speedup 1.0000x reference)
#include <cuda_runtime.h>
#include <math.h>

#define BB 2
#define CC 64
#define HH 192
#define WWD 192
#define HWP 36864
#define NHD 4
#define DDIM 16
#define NSS 144
#define NHSS 12
#define SHH 16
#define NW2 97
#define HW2 18624
#define CH2 128
#define THETA 0.7f
#define ATTNSCALE 0.25f
#define BNINV 0.9999950000374997f

// ---------------- scratch (module-load allocated, allowed) ----------------
static __device__ float g_tabc[HH*HH];
static __device__ float g_tabs[HH*HH];
static __device__ float g_cdsum[CC*CC];
static __device__ float g_contrast[BB*CC*HWP];
static __device__ float g_cent[BB*2*CC*NSS];
static __device__ float g_asum[BB*NSS];
static __device__ float g_aff[BB*9*HWP];
static __device__ float g_xn[BB*CC*HWP];
static __device__ float g_q[BB*CC*HWP];
static __device__ float g_k[BB*CC*HWP];
static __device__ float g_v[BB*CC*HWP];
static __device__ float g_lepe[BB*CC*HWP];
static __device__ float g_stoken[BB*NSS*CC];
static __device__ float g_stok[BB*CC*NSS];
static __device__ float g_sout[BB*CC*NSS];
static __device__ float g_x2[BB*CC*HWP];
static __device__ float g_fw[BB*CC*HH*NW2*2];
static __device__ float g_frb[BB*CH2*HW2];
static __device__ float g_frb2[BB*CH2*HW2];
static __device__ float g_fd[BB*CH2*HW2];
static __device__ float g_gh[BB*CC*HH*NW2*2];

// ---------------- twiddle table: tab[i*192+j] = cos/sin(-2*pi*i*j/192) ----------------
__global__ void k_tab() {
    int t = blockIdx.x * blockDim.x + threadIdx.x;
    if (t >= HH*HH) return;
    int i = t / HH, j = t % HH;
    int r = (i * j) % HH;
    float s, c;
    sincospif(-(float)r / 96.0f, &s, &c);
    g_tabc[t] = c;
    g_tabs[t] = s;
}

__global__ void k_cdsum(const float* __restrict__ cdw) {
    int t = blockIdx.x * blockDim.x + threadIdx.x;
    if (t >= CC*CC) return;
    float s = 0.f;
    #pragma unroll
    for (int k = 0; k < 9; k++) s += cdw[t*9 + k];
    g_cdsum[t] = s;
}

// ---------------- contrast = conv3x3(x, cd_w) - theta * conv1x1(x, sum(cd_w)) ----------------
__global__ void k_contrast(const float* __restrict__ x, const float* __restrict__ cdw) {
    int blk = blockIdx.x;
    int chunk = blk % 144;
    int co = (blk / 144) % CC;
    int b  = blk / (144 * CC);
    __shared__ float ws[CC*9];
    __shared__ float cs[CC];
    for (int i = threadIdx.x; i < CC*9; i += 256) ws[i] = cdw[co*CC*9 + i];
    for (int i = threadIdx.x; i < CC;   i += 256) cs[i] = g_cdsum[co*CC + i];
    __syncthreads();
    int p = chunk * 256 + threadIdx.x;
    int h = p / WWD, w = p % WWD;
    float acc = 0.f, acc2 = 0.f;
    const float* xb = x + (size_t)b * CC * HWP;
    for (int ci = 0; ci < CC; ci++) {
        const float* xc = xb + (size_t)ci * HWP;
        acc2 += cs[ci] * xc[p];
        #pragma unroll
        for (int ky = -1; ky <= 1; ky++) {
            int hh = h + ky;
            if ((unsigned)hh >= HH) continue;
            const float* row = xc + hh * WWD;
            #pragma unroll
            for (int kx = -1; kx <= 1; kx++) {
                int ww = w + kx;
                if ((unsigned)ww >= WWD) continue;
                acc += row[ww] * ws[ci*9 + (ky+1)*3 + (kx+1)];
            }
        }
    }
    g_contrast[((size_t)b*CC + co)*HWP + p] = acc - THETA * acc2;
}

// ---------------- cent init: 16x16 block means of comb=[x; contrast] ----------------
__global__ void k_centinit(const float* __restrict__ x) {
    int t = blockIdx.x * 256 + threadIdx.x;
    if (t >= BB*2*CC*NSS) return;
    int s  = t % NSS;
    int ch = (t / NSS) % (2*CC);
    int b  = t / (NSS * 2 * CC);
    const float* src = (ch < CC) ? (x + ((size_t)b*CC + ch)*HWP)
                                 : (g_contrast + ((size_t)b*CC + (ch-CC))*HWP);
    int r0 = s / NHSS, c0 = s % NHSS;
    float acc = 0.f;
    for (int i = 0; i < SHH; i++) {
        const float* row = src + (r0*SHH + i)*WWD + c0*SHH;
        #pragma unroll
        for (int j = 0; j < SHH; j++) acc += row[j];
    }
    g_cent[t] = acc * (1.0f/256.0f);
}

// ---------------- distances + softmax -> aff (B,9,HW) ----------------
__global__ void k_dist(const float* __restrict__ x) {
    int t = blockIdx.x * 256 + threadIdx.x;
    if (t >= BB*HWP) return;
    int p = t % HWP, b = t / HWP;
    int h = p / WWD, w = p % WWD;
    int r = h / SHH, c = w / SHH;
    float d[9];
    int   cs[9];
    int   val[9];
    #pragma unroll
    for (int j = 0; j < 9; j++) {
        int dy = j/3 - 1, dx = j%3 - 1;
        int rr = r + dy, cc2 = c + dx;
        val[j] = (rr >= 0 && rr < NHSS && cc2 >= 0 && cc2 < NHSS);
        cs[j]  = val[j] ? rr*NHSS + cc2 : 0;
        d[j]   = 0.f;
    }
    const float* cb = g_cent + (size_t)b * 2 * CC * NSS;
    for (int ch = 0; ch < 2*CC; ch++) {
        float pix = (ch < CC) ? x[((size_t)b*CC + ch)*HWP + p]
                              : g_contrast[((size_t)b*CC + ch - CC)*HWP + p];
        float wgt = (ch < CC) ? 1.0f : 10.0f;
        const float* cr = cb + (size_t)ch * NSS;
        #pragma unroll
        for (int j = 0; j < 9; j++) {
            float df = pix - cr[cs[j]];
            d[j] += wgt * df * df;
        }
    }
    float m = 3.0e38f;
    #pragma unroll
    for (int j = 0; j < 9; j++) if (val[j] && d[j] < m) m = d[j];
    float e[9], sum = 0.f;
    #pragma unroll
    for (int j = 0; j < 9; j++) {
        e[j] = val[j] ? __expf(m - d[j]) : 0.f;
        sum += e[j];
    }
    float inv = 1.0f / sum;
    #pragma unroll
    for (int j = 0; j < 9; j++)
        g_aff[((size_t)b*9 + j)*HWP + p] = e[j] * inv;
}

// ---------------- asum[b][s] = sum of scattered aff ----------------
__global__ void k_asum() {
    int t = blockIdx.x * 128 + threadIdx.x;
    if (t >= BB*NSS) return;
    int s = t % NSS, b = t / NSS;
    int r0 = s / NHSS, c0 = s % NHSS;
    float acc = 0.f;
    for (int dy = -1; dy <= 1; dy++) {
        int r = r0 - dy;
        if ((unsigned)r >= NHSS) continue;
        for (int dx = -1; dx <= 1; dx++) {
            int c = c0 - dx;
            if ((unsigned)c >= NHSS) continue;
            int j = (dy+1)*3 + (dx+1);
            const float* ab = g_aff + ((size_t)b*9 + j)*HWP;
            for (int i = 0; i < SHH; i++) {
                const float* row = ab + (r*SHH + i)*WWD + c*SHH;
                #pragma unroll
                for (int jj = 0; jj < SHH; jj++) acc += row[jj];
            }
        }
    }
    g_asum[t] = acc;
}

// ---------------- cent update via gather ----------------
__global__ void k_centupd(const float* __restrict__ x) {
    int t = blockIdx.x * 256 + threadIdx.x;
    if (t >= BB*2*CC*NSS) return;
    int s  = t % NSS;
    int ch = (t / NSS) % (2*CC);
    int b  = t / (NSS * 2 * CC);
    const float* src = (ch < CC) ? (x + ((size_t)b*CC + ch)*HWP)
                                 : (g_contrast + ((size_t)b*CC + (ch-CC))*HWP);
    int r0 = s / NHSS, c0 = s % NHSS;
    float acc = 0.f;
    for (int dy = -1; dy <= 1; dy++) {
        int r = r0 - dy;
        if ((unsigned)r >= NHSS) continue;
        for (int dx = -1; dx <= 1; dx++) {
            int c = c0 - dx;
            if ((unsigned)c >= NHSS) continue;
            int j = (dy+1)*3 + (dx+1);
            const float* ab = g_aff + ((size_t)b*9 + j)*HWP;
            for (int i = 0; i < SHH; i++) {
                int base = (r*SHH + i)*WWD + c*SHH;
                #pragma unroll
                for (int jj = 0; jj < SHH; jj++)
                    acc += ab[base + jj] * src[base + jj];
            }
        }
    }
    g_cent[t] = acc / (g_asum[(size_t)b*NSS + s] + 1e-16f);
}

// ---------------- LayerNorm over channels ----------------
__global__ void k_lnorm(const float* __restrict__ x, const float* __restrict__ g,
                        const float* __restrict__ bta) {
    int t = blockIdx.x * 256 + threadIdx.x;
    if (t >= BB*HWP) return;
    int p = t % HWP, b = t / HWP;
    const float* xb = x + (size_t)b*CC*HWP + p;
    float sum = 0.f, sq = 0.f;
    for (int ch = 0; ch < CC; ch++) {
        float v = xb[(size_t)ch*HWP];
        sum += v; sq += v*v;
    }
    float mu = sum * (1.0f/CC);
    float var = sq * (1.0f/CC) - mu*mu;
    float rstd = rsqrtf(var + 1e-6f);
    float* ob = g_xn + (size_t)b*CC*HWP + p;
    for (int ch = 0; ch < CC; ch++) {
        float v = xb[(size_t)ch*HWP];
        ob[(size_t)ch*HWP] = (v - mu) * rstd * g[ch] + bta[ch];
    }
}

// ---------------- stoken gather (uses final aff + xn) ----------------
__global__ void k_stoken() {
    int t = blockIdx.x * 256 + threadIdx.x;
    if (t >= BB*NSS*CC) return;
    int ch = t % CC;
    int s  = (t / CC) % NSS;
    int b  = t / (CC * NSS);
    const float* src = g_xn + ((size_t)b*CC + ch)*HWP;
    int r0 = s / NHSS, c0 = s % NHSS;
    float acc = 0.f;
    for (int dy = -1; dy <= 1; dy++) {
        int r = r0 - dy;
        if ((unsigned)r >= NHSS) continue;
        for (int dx = -1; dx <= 1; dx++) {
            int c = c0 - dx;
            if ((unsigned)c >= NHSS) continue;
            int j = (dy+1)*3 + (dx+1);
            const float* ab = g_aff + ((size_t)b*9 + j)*HWP;
            for (int i = 0; i < SHH; i++) {
                int base = (r*SHH + i)*WWD + c*SHH;
                #pragma unroll
                for (int jj = 0; jj < SHH; jj++)
                    acc += ab[base + jj] * src[base + jj];
            }
        }
    }
    g_stoken[((size_t)b*NSS + s)*CC + ch] = acc / (g_asum[(size_t)b*NSS + s] + 1e-16f);
}

// ---------------- stok = stoken @ sp_w^T  (layout (b, o, s), o = h*16+d) ----------------
__global__ void k_stokmm(const float* __restrict__ spw) {
    int t = blockIdx.x * 256 + threadIdx.x;
    if (t >= BB*CC*NSS) return;
    int s = t % NSS;
    int o = (t / NSS) % CC;
    int b = t / (NSS * CC);
    const float* st = g_stoken + ((size_t)b*NSS + s)*CC;
    const float* w  = spw + o*CC;
    float acc = 0.f;
    #pragma unroll 8
    for (int c = 0; c < CC; c++) acc += w[c] * st[c];
    g_stok[((size_t)b*CC + o)*NSS + s] = acc;
}

// ---------------- fused q/k/v 1x1 convs on xn ----------------
__global__ void k_qkv(const float* __restrict__ qw, const float* __restrict__ kw,
                      const float* __restrict__ vw) {
    int blk = blockIdx.x;
    int chunk = blk % 144;
    int o = (blk / 144) % 192;
    int b = blk / (144 * 192);
    __shared__ float ws[CC];
    const float* wsrc = (o < 64) ? (qw + o*CC) : (o < 128 ? kw + (o-64)*CC : vw + (o-128)*CC);
    if (threadIdx.x < CC) ws[threadIdx.x] = wsrc[threadIdx.x];
    __syncthreads();
    int p = chunk * 256 + threadIdx.x;
    const float* xb = g_xn + (size_t)b*CC*HWP + p;
    float acc = 0.f;
    #pragma unroll 8
    for (int c = 0; c < CC; c++) acc += ws[c] * xb[(size_t)c*HWP];
    float* dst = (o < 64) ? (g_q + ((size_t)b*64 + o)*HWP)
               : (o < 128 ? (g_k + ((size_t)b*64 + o-64)*HWP)
                          : (g_v + ((size_t)b*64 + o-128)*HWP));
    dst[p] = acc;
}

// ---------------- lepe: depthwise 3x3 on v + bias, permuted write (Tflat layout) ----------------
__global__ void k_lepe(const float* __restrict__ lw, const float* __restrict__ lb) {
    int blk = blockIdx.x;
    int chunk = blk % 144;
    int c = (blk / 144) % CC;
    int b = blk / (144 * CC);
    __shared__ float ws[9];
    if (threadIdx.x < 9) ws[threadIdx.x] = lw[c*9 + threadIdx.x];
    __syncthreads();
    int p = chunk * 256 + threadIdx.x;
    int h = p / WWD, w = p % WWD;
    const float* vb = g_v + ((size_t)b*CC + c)*HWP;
    float acc = lb[c];
    #pragma unroll
    for (int ky = -1; ky <= 1; ky++) {
        int hh = h + ky;
        if ((unsigned)hh >= HH) continue;
        const float* row = vb + hh*WWD;
        #pragma unroll
        for (int kx = -1; kx <= 1; kx++) {
            int ww = w + kx;
            if ((unsigned)ww >= WWD) continue;
            acc += row[ww] * ws[(ky+1)*3 + (kx+1)];
        }
    }
    // Tflat layout: flat index j = p*C + c holds conv[b][c][p]
    g_lepe[(size_t)b*CC*HWP + (size_t)p*CC + c] = acc;
}

// ---------------- s_attn / s_out: flash softmax over p per (b,h,s-tile) ----------------
#define STILE 4
__global__ void __launch_bounds__(256) k_sattn() {
    int blk = blockIdx.x;
    int sg = blk % (NSS/STILE);
    int hh = (blk / (NSS/STILE)) % NHD;
    int b  = blk / ((NSS/STILE) * NHD);
    int s0 = sg * STILE;
    int tid = threadIdx.x;
    __shared__ float stks[STILE][DDIM];
    if (tid < STILE*DDIM) {
        int si = tid / DDIM, d = tid % DDIM;
        stks[si][d] = g_stok[((size_t)(b*NHD + hh)*DDIM + d)*NSS + s0 + si];
    }
    __syncthreads();
    float m[STILE], l[STILE], acc[STILE][DDIM];
    #pragma unroll
    for (int si = 0; si < STILE; si++) {
        m[si] = -3.0e38f; l[si] = 0.f;
        #pragma unroll
        for (int d = 0; d < DDIM; d++) acc[si][d] = 0.f;
    }
    const float* kb = g_k + (size_t)(b*NHD + hh)*DDIM*HWP;
    const float* vb = g_v + (size_t)(b*NHD + hh)*DDIM*HWP;
    for (int p = tid; p < HWP; p += 256) {
        float kd[DDIM], vd[DDIM];
        #pragma unroll
        for (int d = 0; d < DDIM; d++) kd[d] = kb[(size_t)d*HWP + p];
        #pragma unroll
        for (int d = 0; d < DDIM; d++) vd[d] = vb[(size_t)d*HWP + p];
        #pragma unroll
        for (int si = 0; si < STILE; si++) {
            float lg = 0.f;
            #pragma unroll
            for (int d = 0; d < DDIM; d++) lg += kd[d] * stks[si][d];
            lg *= ATTNSCALE;
            if (lg > m[si]) {
                float al = __expf(m[si] - lg);
                l[si] *= al;
                #pragma unroll
                for (int d = 0; d < DDIM; d++) acc[si][d] *= al;
                m[si] = lg;
            }
            float wv = __expf(lg - m[si]);
            l[si] += wv;
            #pragma unroll
            for (int d = 0; d < DDIM; d++) acc[si][d] += wv * vd[d];
        }
    }
    __shared__ float rm[256], rl[256], ra[DDIM*256];
    for (int si = 0; si < STILE; si++) {
        rm[tid] = m[si]; rl[tid] = l[si];
        #pragma unroll
        for (int d = 0; d < DDIM; d++) ra[d*256 + tid] = acc[si][d];
        __syncthreads();
        for (int str = 128; str > 0; str >>= 1) {
            if (tid < str) {
                float mo = rm[tid + str], lo = rl[tid + str];
                float nm = fmaxf(rm[tid], mo);
                float ea = __expf(rm[tid] - nm), eb = __expf(mo - nm);
                rl[tid] = rl[tid]*ea + lo*eb;
                #pragma unroll
                for (int d = 0; d < DDIM; d++)
                    ra[d*256 + tid] = ra[d*256 + tid]*ea + ra[d*256 + tid + str]*eb;
                rm[tid] = nm;
            }
            __syncthreads();
        }
        if (tid < DDIM)
            g_sout[((size_t)(b*NHD + hh)*DDIM + tid)*NSS + s0 + si] = ra[tid*256] / rl[0];
        __syncthreads();
    }
}

// ---------------- x_attn + x2 = x + x_out + lepe ----------------
__global__ void __launch_bounds__(256) k_xattn(const float* __restrict__ x) {
    int blk = blockIdx.x;
    int chunk = blk % 144;
    int hh = (blk / 144) % NHD;
    int b  = blk / (144 * NHD);
    int tid = threadIdx.x;
    __shared__ float st[DDIM*NSS];
    __shared__ float so[DDIM*NSS];
    size_t base = (size_t)(b*NHD + hh)*DDIM*NSS;
    for (int i = tid; i < DDIM*NSS; i += 256) {
        st[i] = g_stok[base + i];
        so[i] = g_sout[base + i];
    }
    __syncthreads();
    int p = chunk * 256 + tid;
    float qd[DDIM];
    #pragma unroll
    for (int d = 0; d < DDIM; d++)
        qd[d] = g_q[((size_t)(b*NHD + hh)*DDIM + d)*HWP + p];
    float m = -3.0e38f, l = 0.f;
    for (int s = 0; s < NSS; s++) {
        float lg = 0.f;
        #pragma unroll
        for (int d = 0; d < DDIM; d++) lg += qd[d] * st[d*NSS + s];
        lg *= ATTNSCALE;
        float nm = fmaxf(m, lg);
        l = l * __expf(m - nm) + __expf(lg - nm);
        m = nm;
    }
    float invl = 1.0f / l;
    float acc[DDIM];
    #pragma unroll
    for (int d = 0; d < DDIM; d++) acc[d] = 0.f;
    for (int s = 0; s < NSS; s++) {
        float lg = 0.f;
        #pragma unroll
        for (int d = 0; d < DDIM; d++) lg += qd[d] * st[d*NSS + s];
        lg *= ATTNSCALE;
        float wv = __expf(lg - m) * invl;
        #pragma unroll
        for (int d = 0; d < DDIM; d++) acc[d] += wv * so[d*NSS + s];
    }
    // reference reshape bug: lepe_final[b][c][p] = Tflat[c*HW + p], Tflat stored in g_lepe
    #pragma unroll
    for (int d = 0; d < DDIM; d++) {
        int cch = hh*DDIM + d;
        size_t o = ((size_t)b*CC + cch)*HWP + p;
        g_x2[o] = x[o] + acc[d] + g_lepe[o];
    }
}

// ---------------- W-dim rfft (unnormalized), 8 rows per block ----------------
__global__ void k_fftw() {
    int blk = blockIdx.x;
    int hg = blk % 24;
    int c  = (blk / 24) % CC;
    int b  = blk / (24 * CC);
    int h0 = hg * 8;
    __shared__ float rows[8][WWD];
    for (int i = threadIdx.x; i < 8*WWD; i += 128)
        rows[i/WWD][i%WWD] = g_x2[((size_t)b*CC + c)*HWP + (size_t)(h0 + i/WWD)*WWD + i%WWD];
    __syncthreads();
    int k = threadIdx.x;
    if (k >= NW2) return;
    float re[8], im[8];
    #pragma unroll
    for (int r = 0; r < 8; r++) { re[r] = 0.f; im[r] = 0.f; }
    for (int w = 0; w < WWD; w++) {
        float tc = g_tabc[w*HH + k], ts = g_tabs[w*HH + k];
        #pragma unroll
        for (int r = 0; r < 8; r++) {
            float v = rows[r][w];
            re[r] += v * tc;
            im[r] += v * ts;
        }
    }
    #pragma unroll
    for (int r = 0; r < 8; r++) {
        size_t o = (((size_t)(b*CC + c)*HH + h0 + r)*NW2 + k)*2;
        g_fw[o] = re[r]; g_fw[o+1] = im[r];
    }
}

// ---------------- H-dim full FFT + ortho scale + BN -> frb (B,2C,H,W2) ----------------
__global__ void k_ffth(const float* __restrict__ bng, const float* __restrict__ bnb) {
    int blk = blockIdx.x;
    int kg = blk % 13;
    int c  = (blk / 13) % CC;
    int b  = blk / (13 * CC);
    int k0 = kg * 8;
    int m = threadIdx.x; // 0..191
    float re[8], im[8];
    #pragma unroll
    for (int kk = 0; kk < 8; kk++) { re[kk] = 0.f; im[kk] = 0.f; }
    __shared__ float2 stage[32*8];
    for (int hc = 0; hc < 6; hc++) {
        for (int i = threadIdx.x; i < 32*8; i += 192) {
            int hh2 = hc*32 + i/8, kk = i % 8;
            float2 v = make_float2(0.f, 0.f);
            if (k0 + kk < NW2) {
                size_t o = (((size_t)(b*CC + c)*HH + hh2)*NW2 + k0 + kk)*2;
                v.x = g_fw[o]; v.y = g_fw[o+1];
            }
            stage[i] = v;
        }
        __syncthreads();
        for (int hi = 0; hi < 32; hi++) {
            int hh2 = hc*32 + hi;
            float tc = g_tabc[hh2*HH + m], ts = g_tabs[hh2*HH + m];
            #pragma unroll
            for (int kk = 0; kk < 8; kk++) {
                float2 f = stage[hi*8 + kk];
                re[kk] += f.x*tc - f.y*ts;
                im[kk] += f.x*ts + f.y*tc;
            }
        }
        __syncthreads();
    }
    const float sc = 1.0f / 192.0f;
    int chR = 2*c, chI = 2*c + 1;
    float gr = BNINV * bng[chR], br = bnb[chR];
    float gi = BNINV * bng[chI], bi = bnb[chI];
    for (int kk = 0; kk < 8; kk++) {
        int k = k0 + kk;
        if (k >= NW2) break;
        g_frb[((size_t)(b*CH2 + chR)*HH + m)*NW2 + k] = re[kk]*sc*gr + br;
        g_frb[((size_t)(b*CH2 + chI)*HH + m)*NW2 + k] = im[kk]*sc*gi + bi;
    }
}

// ---------------- fpe: depthwise 3x3 + bias + residual on (H, W2) ----------------
__global__ void k_fpe(const float* __restrict__ fw, const float* __restrict__ fb) {
    int t = blockIdx.x * 256 + threadIdx.x;
    if (t >= BB*CH2*HW2) return;
    int k  = t % NW2;
    int m  = (t / NW2) % HH;
    int ch = (t / HW2) % CH2;
    const float* base = g_frb + (size_t)(t / HW2) * HW2;
    float acc = fb[ch];
    #pragma unroll
    for (int ky = -1; ky <= 1; ky++) {
        int mm = m + ky;
        if ((unsigned)mm >= HH) continue;
        #pragma unroll
        for (int kx = -1; kx <= 1; kx++) {
            int kk2 = k + kx;
            if ((unsigned)kk2 >= NW2) continue;
            acc += base[mm*NW2 + kk2] * fw[ch*9 + (ky+1)*3 + (kx+1)];
        }
    }
    g_frb2[t] = acc + base[m*NW2 + k];
}

// ---------------- fdc 1x1 conv (128->128) + exact GELU (dyw == 1) ----------------
__global__ void k_fdc(const float* __restrict__ fw, const float* __restrict__ fb) {
    int blk = blockIdx.x;
    int chunk = blk % 73;
    int o = (blk / 73) % CH2;
    int b = blk / (73 * CH2);
    __shared__ float ws[CH2];
    for (int i = threadIdx.x; i < CH2; i += 256) ws[i] = fw[o*CH2 + i];
    __syncthreads();
    int p = chunk * 256 + threadIdx.x;
    if (p >= HW2) return;
    const float* xb = g_frb2 + (size_t)b*CH2*HW2 + p;
    float acc = fb[o];
    #pragma unroll 8
    for (int c = 0; c < CH2; c++) acc += ws[c] * xb[(size_t)c*HW2];
    float gl = 0.5f * acc * (1.0f + erff(acc * 0.70710678118654752f));
    g_fd[((size_t)b*CH2 + o)*HW2 + p] = gl;
}

// ---------------- inverse H-dim FFT (e^{+i}), unnormalized ----------------
__global__ void k_invh() {
    int blk = blockIdx.x;
    int kg = blk % 13;
    int c  = (blk / 13) % CC;
    int b  = blk / (13 * CC);
    int k0 = kg * 8;
    int h = threadIdx.x; // 0..191
    float re[8], im[8];
    #pragma unroll
    for (int kk = 0; kk < 8; kk++) { re[kk] = 0.f; im[kk] = 0.f; }
    const float* fR = g_fd + (size_t)(b*CH2 + 2*c)*HW2;
    const float* fI = g_fd + (size_t)(b*CH2 + 2*c + 1)*HW2;
    __shared__ float2 stage[32*8];
    for (int mc = 0; mc < 6; mc++) {
        for (int i = threadIdx.x; i < 32*8; i += 192) {
            int mm = mc*32 + i/8, kk = i % 8;
            float2 v = make_float2(0.f, 0.f);
            if (k0 + kk < NW2) {
                v.x = fR[mm*NW2 + k0 + kk];
                v.y = fI[mm*NW2 + k0 + kk];
            }
            stage[i] = v;
        }
        __syncthreads();
        for (int mi = 0; mi < 32; mi++) {
            int mm = mc*32 + mi;
            float tc = g_tabc[mm*HH + h], ts = g_tabs[mm*HH + h];
            #pragma unroll
            for (int kk = 0; kk < 8; kk++) {
                float2 f = stage[mi*8 + kk];
                re[kk] += f.x*tc + f.y*ts;   // Re(F * e^{+i theta}); table holds e^{-i}
                im[kk] += f.y*tc - f.x*ts;
            }
        }
        __syncthreads();
    }
    for (int kk = 0; kk < 8; kk++) {
        int k = k0 + kk;
        if (k >= NW2) break;
        size_t o = (((size_t)(b*CC + c)*HH + h)*NW2 + k)*2;
        g_gh[o] = re[kk]; g_gh[o+1] = im[kk];
    }
}

// ---------------- irfft over W + xc branch + final output ----------------
__global__ void k_final(const float* __restrict__ xcw, const float* __restrict__ xcb,
                        const float* __restrict__ bn2g, const float* __restrict__ bn2b,
                        float* __restrict__ out) {
    int blk = blockIdx.x;
    int hg = blk % 24;
    int c  = (blk / 24) % CC;
    int b  = blk / (24 * CC);
    int h0 = hg * 8;
    __shared__ float ghr[8][NW2];
    __shared__ float ghi[8][NW2];
    __shared__ float xws[CC];
    for (int i = threadIdx.x; i < 8*NW2; i += 192) {
        int r = i / NW2, k = i % NW2;
        size_t o = (((size_t)(b*CC + c)*HH + h0 + r)*NW2 + k)*2;
        ghr[r][k] = g_gh[o];
        ghi[r][k] = g_gh[o+1];
    }
    if (threadIdx.x < CC) xws[threadIdx.x] = xcw[c*CC + threadIdx.x];
    __syncthreads();
    int w = threadIdx.x;
    float acc[8];
    #pragma unroll
    for (int r = 0; r < 8; r++) acc[r] = 0.f;
    for (int k = 1; k < 96; k++) {
        float tc = g_tabc[k*HH + w], ts = g_tabs[k*HH + w];
        #pragma unroll
        for (int r = 0; r < 8; r++)
            acc[r] += ghr[r][k]*tc + ghi[r][k]*ts;
    }
    float xacc[8];
    #pragma unroll
    for (int r = 0; r < 8; r++) xacc[r] = 0.f;
    const float* x2b = g_x2 + (size_t)b*CC*HWP + (size_t)h0*WWD + w;
    for (int c2 = 0; c2 < CC; c2++) {
        float wv = xws[c2];
        const float* xp = x2b + (size_t)c2*HWP;
        #pragma unroll
        for (int r = 0; r < 8; r++) xacc[r] += wv * xp[r*WWD];
    }
    float par = (w & 1) ? -1.0f : 1.0f;
    float xb2 = xcb[c];
    float gg = BNINV * bn2g[c], bbq = bn2b[c];
    #pragma unroll
    for (int r = 0; r < 8; r++) {
        float of = (ghr[r][0] + ghr[r][96]*par + 2.0f*acc[r]) * (1.0f/192.0f);
        float xa = (xacc[r] + xb2) * gg + bbq;
        out[((size_t)b*CC + c)*HWP + (size_t)(h0 + r)*WWD + w] = fmaxf(xa, 0.0f) + of;
    }
}

// ---------------- launch ----------------
extern "C" void kernel_launch(void* const* d_in, const int* in_sizes, int n_in,
                              void* d_out, int out_size) {
    const float* x    = (const float*)d_in[0];
    const float* cdw  = (const float*)d_in[1];
    const float* lng  = (const float*)d_in[2];
    const float* lnb  = (const float*)d_in[3];
    const float* qw   = (const float*)d_in[4];
    const float* kw   = (const float*)d_in[5];
    const float* vw   = (const float*)d_in[6];
    const float* spw  = (const float*)d_in[7];
    const float* lw   = (const float*)d_in[8];
    const float* lb   = (const float*)d_in[9];
    const float* bng  = (const float*)d_in[10];
    const float* bnb  = (const float*)d_in[11];
    const float* fpew = (const float*)d_in[12];
    const float* fpeb = (const float*)d_in[13];
    // d_in[14], d_in[15] = wt_w, wt_b : dyw = softmax over 1 channel == 1, unused
    const float* fdcw = (const float*)d_in[16];
    const float* fdcb = (const float*)d_in[17];
    const float* xcw  = (const float*)d_in[18];
    const float* xcb  = (const float*)d_in[19];
    const float* bn2g = (const float*)d_in[20];
    const float* bn2b = (const float*)d_in[21];
    float* out = (float*)d_out;

    k_tab<<<144, 256>>>();
    k_cdsum<<<16, 256>>>(cdw);
    k_contrast<<<BB*CC*144, 256>>>(x, cdw);
    k_centinit<<<144, 256>>>(x);
    k_dist<<<288, 256>>>(x);
    k_asum<<<3, 128>>>();
    k_centupd<<<144, 256>>>(x);
    k_dist<<<288, 256>>>(x);
    k_asum<<<3, 128>>>();
    k_lnorm<<<288, 256>>>(x, lng, lnb);
    k_stoken<<<72, 256>>>();
    k_stokmm<<<72, 256>>>(spw);
    k_qkv<<<BB*192*144, 256>>>(qw, kw, vw);
    k_lepe<<<BB*CC*144, 256>>>(lw, lb);
    k_sattn<<<BB*NHD*(NSS/STILE), 256>>>();
    k_xattn<<<BB*NHD*144, 256>>>(x);
    k_fftw<<<BB*CC*24, 128>>>();
    k_ffth<<<BB*CC*13, 192>>>(bng, bnb);
    k_fpe<<<(BB*CH2*HW2 + 255)/256, 256>>>(fpew, fpeb);
    k_fdc<<<BB*CH2*73, 256>>>(fdcw, fdcb);
    k_invh<<<BB*CC*13, 192>>>();
    k_final<<<BB*CC*24, 192>>>(xcw, xcb, bn2g, bn2b, out);
}

// round 5
// speedup vs baseline: 1.4860x; 1.4860x over previous
#include <cuda_runtime.h>
#include <math.h>

#define BB 2
#define CC 64
#define HH 192
#define WWD 192
#define HWP 36864
#define NHD 4
#define DDIM 16
#define NSS 144
#define NHSS 12
#define SHH 16
#define NW2 97
#define HW2 18624
#define CH2 128
#define THETA 0.7f
#define ATTNSCALE 0.25f
#define BNINV 0.9999950000374997f

// ---------------- scratch ----------------
static __device__ float g_tabc[HH*HH];
static __device__ float g_tabs[HH*HH];
static __device__ float g_cdsum[CC*CC];
static __device__ float g_contrast[BB*CC*HWP];
static __device__ float g_cent[BB*2*CC*NSS];
static __device__ float g_asum[BB*NSS];
static __device__ float g_aff[BB*9*HWP];
static __device__ float g_xn[BB*CC*HWP];
static __device__ float g_q[BB*CC*HWP];
static __device__ float g_k[BB*CC*HWP];
static __device__ float g_v[BB*CC*HWP];
static __device__ float g_lepe[BB*CC*HWP];
static __device__ float g_stoken[BB*NSS*CC];
static __device__ float g_stok[BB*CC*NSS];
static __device__ float g_sout[BB*CC*NSS];
static __device__ float g_x2[BB*CC*HWP];
static __device__ float g_fw[BB*CC*HH*NW2*2];
static __device__ float g_frb[BB*CH2*HW2];
static __device__ float g_frb2[BB*CH2*HW2];
static __device__ float g_fd[BB*CH2*HW2];
static __device__ float g_gh[BB*CC*HH*NW2*2];

// ---------------- twiddle table ----------------
__global__ void k_tab() {
    int t = blockIdx.x * blockDim.x + threadIdx.x;
    if (t >= HH*HH) return;
    int i = t / HH, j = t % HH;
    int r = (i * j) % HH;
    float s, c;
    sincospif(-(float)r / 96.0f, &s, &c);
    g_tabc[t] = c;
    g_tabs[t] = s;
}

__global__ void k_cdsum(const float* __restrict__ cdw) {
    int t = blockIdx.x * blockDim.x + threadIdx.x;
    if (t >= CC*CC) return;
    float s = 0.f;
    #pragma unroll
    for (int k = 0; k < 9; k++) s += cdw[t*9 + k];
    g_cdsum[t] = s;
}

// ---------------- contrast: 16 output channels per block, weights in smem ----------------
__global__ void __launch_bounds__(256) k_contrast(const float* __restrict__ x,
                                                  const float* __restrict__ cdw) {
    int blk = blockIdx.x;
    int chunk = blk % 144;
    int og = (blk / 144) % 4;
    int b  = blk / (144 * 4);
    // ws[ci][tap][o]: tap 0..8 = stencil, tap 9 = -theta*cdsum
    __shared__ float ws[CC][10][16];
    for (int i = threadIdx.x; i < CC*10*16; i += 256) {
        int o = i % 16;
        int tap = (i / 16) % 10;
        int ci = i / 160;
        int oo = og*16 + o;
        ws[ci][tap][o] = (tap < 9) ? cdw[((size_t)oo*CC + ci)*9 + tap]
                                   : -THETA * g_cdsum[oo*CC + ci];
    }
    __syncthreads();
    int p = chunk * 256 + threadIdx.x;
    int h = p / WWD, w = p % WWD;
    float acc[16];
    #pragma unroll
    for (int o = 0; o < 16; o++) acc[o] = 0.f;
    const float* xb = x + (size_t)b * CC * HWP;
    for (int ci = 0; ci < CC; ci++) {
        const float* xc = xb + (size_t)ci * HWP;
        float xv[10];
        #pragma unroll
        for (int ky = 0; ky < 3; ky++) {
            int hh = h + ky - 1;
            #pragma unroll
            for (int kx = 0; kx < 3; kx++) {
                int ww = w + kx - 1;
                xv[ky*3+kx] = ((unsigned)hh < HH && (unsigned)ww < WWD) ? xc[hh*WWD + ww] : 0.f;
            }
        }
        xv[9] = xv[4];  // center for cdsum term
        #pragma unroll
        for (int tap = 0; tap < 10; tap++) {
            float v = xv[tap];
            const float4* wp = (const float4*)&ws[ci][tap][0];
            #pragma unroll
            for (int q = 0; q < 4; q++) {
                float4 w4 = wp[q];
                acc[q*4+0] += v * w4.x;
                acc[q*4+1] += v * w4.y;
                acc[q*4+2] += v * w4.z;
                acc[q*4+3] += v * w4.w;
            }
        }
    }
    #pragma unroll
    for (int o = 0; o < 16; o++)
        g_contrast[((size_t)b*CC + og*16 + o)*HWP + p] = acc[o];
}

// ---------------- cent init ----------------
__global__ void k_centinit(const float* __restrict__ x) {
    int t = blockIdx.x * 256 + threadIdx.x;
    if (t >= BB*2*CC*NSS) return;
    int s  = t % NSS;
    int ch = (t / NSS) % (2*CC);
    int b  = t / (NSS * 2 * CC);
    const float* src = (ch < CC) ? (x + ((size_t)b*CC + ch)*HWP)
                                 : (g_contrast + ((size_t)b*CC + (ch-CC))*HWP);
    int r0 = s / NHSS, c0 = s % NHSS;
    float acc = 0.f;
    for (int i = 0; i < SHH; i++) {
        const float* row = src + (r0*SHH + i)*WWD + c0*SHH;
        #pragma unroll
        for (int j = 0; j < SHH; j++) acc += row[j];
    }
    g_cent[t] = acc * (1.0f/256.0f);
}

// ---------------- distances + softmax -> aff ----------------
__global__ void k_dist(const float* __restrict__ x) {
    int t = blockIdx.x * 256 + threadIdx.x;
    if (t >= BB*HWP) return;
    int p = t % HWP, b = t / HWP;
    int h = p / WWD, w = p % WWD;
    int r = h / SHH, c = w / SHH;
    float d[9];
    int   cs[9];
    int   val[9];
    #pragma unroll
    for (int j = 0; j < 9; j++) {
        int dy = j/3 - 1, dx = j%3 - 1;
        int rr = r + dy, cc2 = c + dx;
        val[j] = (rr >= 0 && rr < NHSS && cc2 >= 0 && cc2 < NHSS);
        cs[j]  = val[j] ? rr*NHSS + cc2 : 0;
        d[j]   = 0.f;
    }
    const float* cb = g_cent + (size_t)b * 2 * CC * NSS;
    for (int ch = 0; ch < 2*CC; ch++) {
        float pix = (ch < CC) ? x[((size_t)b*CC + ch)*HWP + p]
                              : g_contrast[((size_t)b*CC + ch - CC)*HWP + p];
        float wgt = (ch < CC) ? 1.0f : 10.0f;
        const float* cr = cb + (size_t)ch * NSS;
        #pragma unroll
        for (int j = 0; j < 9; j++) {
            float df = pix - cr[cs[j]];
            d[j] += wgt * df * df;
        }
    }
    float m = 3.0e38f;
    #pragma unroll
    for (int j = 0; j < 9; j++) if (val[j] && d[j] < m) m = d[j];
    float e[9], sum = 0.f;
    #pragma unroll
    for (int j = 0; j < 9; j++) {
        e[j] = val[j] ? __expf(m - d[j]) : 0.f;
        sum += e[j];
    }
    float inv = 1.0f / sum;
    #pragma unroll
    for (int j = 0; j < 9; j++)
        g_aff[((size_t)b*9 + j)*HWP + p] = e[j] * inv;
}

// ---------------- asum ----------------
__global__ void k_asum() {
    int t = blockIdx.x * 128 + threadIdx.x;
    if (t >= BB*NSS) return;
    int s = t % NSS, b = t / NSS;
    int r0 = s / NHSS, c0 = s % NHSS;
    float acc = 0.f;
    for (int dy = -1; dy <= 1; dy++) {
        int r = r0 - dy;
        if ((unsigned)r >= NHSS) continue;
        for (int dx = -1; dx <= 1; dx++) {
            int c = c0 - dx;
            if ((unsigned)c >= NHSS) continue;
            int j = (dy+1)*3 + (dx+1);
            const float* ab = g_aff + ((size_t)b*9 + j)*HWP;
            for (int i = 0; i < SHH; i++) {
                const float* row = ab + (r*SHH + i)*WWD + c*SHH;
                #pragma unroll
                for (int jj = 0; jj < SHH; jj++) acc += row[jj];
            }
        }
    }
    g_asum[t] = acc;
}

// ---------------- cent update ----------------
__global__ void k_centupd(const float* __restrict__ x) {
    int t = blockIdx.x * 256 + threadIdx.x;
    if (t >= BB*2*CC*NSS) return;
    int s  = t % NSS;
    int ch = (t / NSS) % (2*CC);
    int b  = t / (NSS * 2 * CC);
    const float* src = (ch < CC) ? (x + ((size_t)b*CC + ch)*HWP)
                                 : (g_contrast + ((size_t)b*CC + (ch-CC))*HWP);
    int r0 = s / NHSS, c0 = s % NHSS;
    float acc = 0.f;
    for (int dy = -1; dy <= 1; dy++) {
        int r = r0 - dy;
        if ((unsigned)r >= NHSS) continue;
        for (int dx = -1; dx <= 1; dx++) {
            int c = c0 - dx;
            if ((unsigned)c >= NHSS) continue;
            int j = (dy+1)*3 + (dx+1);
            const float* ab = g_aff + ((size_t)b*9 + j)*HWP;
            for (int i = 0; i < SHH; i++) {
                int base = (r*SHH + i)*WWD + c*SHH;
                #pragma unroll
                for (int jj = 0; jj < SHH; jj++)
                    acc += ab[base + jj] * src[base + jj];
            }
        }
    }
    g_cent[t] = acc / (g_asum[(size_t)b*NSS + s] + 1e-16f);
}

// ---------------- LayerNorm ----------------
__global__ void k_lnorm(const float* __restrict__ x, const float* __restrict__ g,
                        const float* __restrict__ bta) {
    int t = blockIdx.x * 256 + threadIdx.x;
    if (t >= BB*HWP) return;
    int p = t % HWP, b = t / HWP;
    const float* xb = x + (size_t)b*CC*HWP + p;
    float sum = 0.f, sq = 0.f;
    for (int ch = 0; ch < CC; ch++) {
        float v = xb[(size_t)ch*HWP];
        sum += v; sq += v*v;
    }
    float mu = sum * (1.0f/CC);
    float var = sq * (1.0f/CC) - mu*mu;
    float rstd = rsqrtf(var + 1e-6f);
    float* ob = g_xn + (size_t)b*CC*HWP + p;
    for (int ch = 0; ch < CC; ch++) {
        float v = xb[(size_t)ch*HWP];
        ob[(size_t)ch*HWP] = (v - mu) * rstd * g[ch] + bta[ch];
    }
}

// ---------------- stoken gather ----------------
__global__ void k_stoken() {
    int t = blockIdx.x * 256 + threadIdx.x;
    if (t >= BB*NSS*CC) return;
    int ch = t % CC;
    int s  = (t / CC) % NSS;
    int b  = t / (CC * NSS);
    const float* src = g_xn + ((size_t)b*CC + ch)*HWP;
    int r0 = s / NHSS, c0 = s % NHSS;
    float acc = 0.f;
    for (int dy = -1; dy <= 1; dy++) {
        int r = r0 - dy;
        if ((unsigned)r >= NHSS) continue;
        for (int dx = -1; dx <= 1; dx++) {
            int c = c0 - dx;
            if ((unsigned)c >= NHSS) continue;
            int j = (dy+1)*3 + (dx+1);
            const float* ab = g_aff + ((size_t)b*9 + j)*HWP;
            for (int i = 0; i < SHH; i++) {
                int base = (r*SHH + i)*WWD + c*SHH;
                #pragma unroll
                for (int jj = 0; jj < SHH; jj++)
                    acc += ab[base + jj] * src[base + jj];
            }
        }
    }
    g_stoken[((size_t)b*NSS + s)*CC + ch] = acc / (g_asum[(size_t)b*NSS + s] + 1e-16f);
}

// ---------------- stok = stoken @ sp_w^T ----------------
__global__ void k_stokmm(const float* __restrict__ spw) {
    int t = blockIdx.x * 256 + threadIdx.x;
    if (t >= BB*CC*NSS) return;
    int s = t % NSS;
    int o = (t / NSS) % CC;
    int b = t / (NSS * CC);
    const float* st = g_stoken + ((size_t)b*NSS + s)*CC;
    const float* w  = spw + o*CC;
    float acc = 0.f;
    #pragma unroll 8
    for (int c = 0; c < CC; c++) acc += w[c] * st[c];
    g_stok[((size_t)b*CC + o)*NSS + s] = acc;
}

// ---------------- q/k/v: 16 outputs per block ----------------
__global__ void __launch_bounds__(256) k_qkv(const float* __restrict__ qw,
                                             const float* __restrict__ kw,
                                             const float* __restrict__ vw) {
    int blk = blockIdx.x;
    int chunk = blk % 144;
    int og = (blk / 144) % 12;
    int b  = blk / (144 * 12);
    __shared__ float ws[CC][16];
    for (int i = threadIdx.x; i < CC*16; i += 256) {
        int o = i % 16, ci = i / 16;
        int oo = og*16 + o;
        const float* wsrc = (oo < 64) ? (qw + oo*CC)
                          : (oo < 128 ? kw + (oo-64)*CC : vw + (oo-128)*CC);
        ws[ci][o] = wsrc[ci];
    }
    __syncthreads();
    int p = chunk * 256 + threadIdx.x;
    const float* xb = g_xn + (size_t)b*CC*HWP + p;
    float acc[16];
    #pragma unroll
    for (int o = 0; o < 16; o++) acc[o] = 0.f;
    for (int ci = 0; ci < CC; ci++) {
        float v = xb[(size_t)ci*HWP];
        const float4* wp = (const float4*)&ws[ci][0];
        #pragma unroll
        for (int q = 0; q < 4; q++) {
            float4 w4 = wp[q];
            acc[q*4+0] += v * w4.x;
            acc[q*4+1] += v * w4.y;
            acc[q*4+2] += v * w4.z;
            acc[q*4+3] += v * w4.w;
        }
    }
    #pragma unroll
    for (int o = 0; o < 16; o++) {
        int oo = og*16 + o;
        float* dst = (oo < 64) ? (g_q + ((size_t)b*64 + oo)*HWP)
                   : (oo < 128 ? (g_k + ((size_t)b*64 + oo-64)*HWP)
                               : (g_v + ((size_t)b*64 + oo-128)*HWP));
        dst[p] = acc[o];
    }
}

// ---------------- lepe: depthwise 3x3 on v, permuted write (Tflat layout) ----------------
__global__ void k_lepe(const float* __restrict__ lw, const float* __restrict__ lb) {
    int blk = blockIdx.x;
    int chunk = blk % 144;
    int c = (blk / 144) % CC;
    int b = blk / (144 * CC);
    __shared__ float ws[9];
    if (threadIdx.x < 9) ws[threadIdx.x] = lw[c*9 + threadIdx.x];
    __syncthreads();
    int p = chunk * 256 + threadIdx.x;
    int h = p / WWD, w = p % WWD;
    const float* vb = g_v + ((size_t)b*CC + c)*HWP;
    float acc = lb[c];
    #pragma unroll
    for (int ky = -1; ky <= 1; ky++) {
        int hh = h + ky;
        if ((unsigned)hh >= HH) continue;
        const float* row = vb + hh*WWD;
        #pragma unroll
        for (int kx = -1; kx <= 1; kx++) {
            int ww = w + kx;
            if ((unsigned)ww >= WWD) continue;
            acc += row[ww] * ws[(ky+1)*3 + (kx+1)];
        }
    }
    g_lepe[(size_t)b*CC*HWP + (size_t)p*CC + c] = acc;
}

// ---------------- s_attn: no-max softmax over p (logits provably tiny) ----------------
#define STILE 4
__global__ void __launch_bounds__(256) k_sattn() {
    int blk = blockIdx.x;
    int sg = blk % (NSS/STILE);
    int hh = (blk / (NSS/STILE)) % NHD;
    int b  = blk / ((NSS/STILE) * NHD);
    int s0 = sg * STILE;
    int tid = threadIdx.x;
    __shared__ float stks[STILE][DDIM];
    if (tid < STILE*DDIM) {
        int si = tid / DDIM, d = tid % DDIM;
        stks[si][d] = g_stok[((size_t)(b*NHD + hh)*DDIM + d)*NSS + s0 + si];
    }
    __syncthreads();
    float l[STILE], acc[STILE][DDIM];
    #pragma unroll
    for (int si = 0; si < STILE; si++) {
        l[si] = 0.f;
        #pragma unroll
        for (int d = 0; d < DDIM; d++) acc[si][d] = 0.f;
    }
    const float* kb = g_k + (size_t)(b*NHD + hh)*DDIM*HWP;
    const float* vb = g_v + (size_t)(b*NHD + hh)*DDIM*HWP;
    for (int p = tid; p < HWP; p += 256) {
        float kd[DDIM], vd[DDIM];
        #pragma unroll
        for (int d = 0; d < DDIM; d++) kd[d] = kb[(size_t)d*HWP + p];
        #pragma unroll
        for (int d = 0; d < DDIM; d++) vd[d] = vb[(size_t)d*HWP + p];
        #pragma unroll
        for (int si = 0; si < STILE; si++) {
            float lg = 0.f;
            #pragma unroll
            for (int d = 0; d < DDIM; d++) lg += kd[d] * stks[si][d];
            float e = __expf(lg * ATTNSCALE);
            l[si] += e;
            #pragma unroll
            for (int d = 0; d < DDIM; d++) acc[si][d] += e * vd[d];
        }
    }
    __shared__ float rl[256], ra[DDIM*256];
    for (int si = 0; si < STILE; si++) {
        rl[tid] = l[si];
        #pragma unroll
        for (int d = 0; d < DDIM; d++) ra[d*256 + tid] = acc[si][d];
        __syncthreads();
        for (int str = 128; str > 0; str >>= 1) {
            if (tid < str) {
                rl[tid] += rl[tid + str];
                #pragma unroll
                for (int d = 0; d < DDIM; d++)
                    ra[d*256 + tid] += ra[d*256 + tid + str];
            }
            __syncthreads();
        }
        if (tid < DDIM)
            g_sout[((size_t)(b*NHD + hh)*DDIM + tid)*NSS + s0 + si] = ra[tid*256] / rl[0];
        __syncthreads();
    }
}

// ---------------- x_attn single-pass + x2 = x + x_out + lepe ----------------
__global__ void __launch_bounds__(256) k_xattn(const float* __restrict__ x) {
    int blk = blockIdx.x;
    int chunk = blk % 144;
    int hh = (blk / 144) % NHD;
    int b  = blk / (144 * NHD);
    int tid = threadIdx.x;
    __shared__ float st[DDIM*NSS];
    __shared__ float so[DDIM*NSS];
    size_t base = (size_t)(b*NHD + hh)*DDIM*NSS;
    for (int i = tid; i < DDIM*NSS; i += 256) {
        st[i] = g_stok[base + i];
        so[i] = g_sout[base + i];
    }
    __syncthreads();
    int p = chunk * 256 + tid;
    float qd[DDIM];
    #pragma unroll
    for (int d = 0; d < DDIM; d++)
        qd[d] = g_q[((size_t)(b*NHD + hh)*DDIM + d)*HWP + p];
    float l = 0.f;
    float acc[DDIM];
    #pragma unroll
    for (int d = 0; d < DDIM; d++) acc[d] = 0.f;
    for (int s = 0; s < NSS; s++) {
        float lg = 0.f;
        #pragma unroll
        for (int d = 0; d < DDIM; d++) lg += qd[d] * st[d*NSS + s];
        float e = __expf(lg * ATTNSCALE);
        l += e;
        #pragma unroll
        for (int d = 0; d < DDIM; d++) acc[d] += e * so[d*NSS + s];
    }
    float invl = 1.0f / l;
    #pragma unroll
    for (int d = 0; d < DDIM; d++) {
        int cch = hh*DDIM + d;
        size_t o = ((size_t)b*CC + cch)*HWP + p;
        g_x2[o] = x[o] + acc[d]*invl + g_lepe[o];
    }
}

// ---------------- W-dim rfft, 8 rows per block ----------------
__global__ void k_fftw() {
    int blk = blockIdx.x;
    int hg = blk % 24;
    int c  = (blk / 24) % CC;
    int b  = blk / (24 * CC);
    int h0 = hg * 8;
    __shared__ float rows[8][WWD];
    for (int i = threadIdx.x; i < 8*WWD; i += 128)
        rows[i/WWD][i%WWD] = g_x2[((size_t)b*CC + c)*HWP + (size_t)(h0 + i/WWD)*WWD + i%WWD];
    __syncthreads();
    int k = threadIdx.x;
    if (k >= NW2) return;
    float re[8], im[8];
    #pragma unroll
    for (int r = 0; r < 8; r++) { re[r] = 0.f; im[r] = 0.f; }
    for (int w = 0; w < WWD; w++) {
        float tc = g_tabc[w*HH + k], ts = g_tabs[w*HH + k];
        #pragma unroll
        for (int r = 0; r < 8; r++) {
            float v = rows[r][w];
            re[r] += v * tc;
            im[r] += v * ts;
        }
    }
    #pragma unroll
    for (int r = 0; r < 8; r++) {
        size_t o = (((size_t)(b*CC + c)*HH + h0 + r)*NW2 + k)*2;
        g_fw[o] = re[r]; g_fw[o+1] = im[r];
    }
}

// ---------------- H-dim FFT, even/odd DIT split + BN -> frb ----------------
__global__ void k_ffth(const float* __restrict__ bng, const float* __restrict__ bnb) {
    int blk = blockIdx.x;
    int kg = blk % 13;
    int c  = (blk / 13) % CC;
    int b  = blk / (13 * CC);
    int k0 = kg * 8;
    int t = threadIdx.x; // 0..191
    int isO = (t >= 96);
    int u = isO ? t - 96 : t;
    float re[8], im[8];
    #pragma unroll
    for (int kk = 0; kk < 8; kk++) { re[kk] = 0.f; im[kk] = 0.f; }
    __shared__ float2 stage[32*8];
    for (int hc = 0; hc < 6; hc++) {
        for (int i = threadIdx.x; i < 32*8; i += 192) {
            int hh2 = hc*32 + i/8, kk = i % 8;
            float2 v = make_float2(0.f, 0.f);
            if (k0 + kk < NW2) {
                size_t o = (((size_t)(b*CC + c)*HH + hh2)*NW2 + k0 + kk)*2;
                v.x = g_fw[o]; v.y = g_fw[o+1];
            }
            stage[i] = v;
        }
        __syncthreads();
        for (int hi = isO ? 1 : 0; hi < 32; hi += 2) {
            int h = hc*32 + hi;
            int trow = isO ? (h - 1) : h;
            float tc = g_tabc[trow*HH + u], ts = g_tabs[trow*HH + u];
            #pragma unroll
            for (int kk = 0; kk < 8; kk++) {
                float2 f = stage[hi*8 + kk];
                re[kk] += f.x*tc - f.y*ts;
                im[kk] += f.x*ts + f.y*tc;
            }
        }
        __syncthreads();
    }
    __shared__ float2 EO[192][8];
    #pragma unroll
    for (int kk = 0; kk < 8; kk++) EO[t][kk] = make_float2(re[kk], im[kk]);
    __syncthreads();
    // X_u = E_u + w^u O_u ; X_{u+96} = E_u - w^u O_u ; thread t outputs m=t
    float wc = g_tabc[HH + u], wsn = g_tabs[HH + u]; // w^u
    float sgn = isO ? -1.f : 1.f;
    const float sc = 1.0f / 192.0f;
    int chR = 2*c, chI = 2*c + 1;
    float gr = BNINV * bng[chR], br = bnb[chR];
    float gi = BNINV * bng[chI], bi = bnb[chI];
    int m = t;
    for (int kk = 0; kk < 8; kk++) {
        int k = k0 + kk;
        if (k >= NW2) break;
        float2 E = EO[u][kk], O = EO[96 + u][kk];
        float orx = O.x*wc - O.y*wsn;
        float ory = O.x*wsn + O.y*wc;
        float Xr = E.x + sgn*orx;
        float Xi = E.y + sgn*ory;
        g_frb[((size_t)(b*CH2 + chR)*HH + m)*NW2 + k] = Xr*sc*gr + br;
        g_frb[((size_t)(b*CH2 + chI)*HH + m)*NW2 + k] = Xi*sc*gi + bi;
    }
}

// ---------------- fpe: depthwise 3x3 + residual ----------------
__global__ void k_fpe(const float* __restrict__ fw, const float* __restrict__ fb) {
    int t = blockIdx.x * 256 + threadIdx.x;
    if (t >= BB*CH2*HW2) return;
    int k  = t % NW2;
    int m  = (t / NW2) % HH;
    int ch = (t / HW2) % CH2;
    const float* base = g_frb + (size_t)(t / HW2) * HW2;
    float acc = fb[ch];
    #pragma unroll
    for (int ky = -1; ky <= 1; ky++) {
        int mm = m + ky;
        if ((unsigned)mm >= HH) continue;
        #pragma unroll
        for (int kx = -1; kx <= 1; kx++) {
            int kk2 = k + kx;
            if ((unsigned)kk2 >= NW2) continue;
            acc += base[mm*NW2 + kk2] * fw[ch*9 + (ky+1)*3 + (kx+1)];
        }
    }
    g_frb2[t] = acc + base[m*NW2 + k];
}

// ---------------- fdc: 16 outputs per block + GELU ----------------
__global__ void __launch_bounds__(256) k_fdc(const float* __restrict__ fw,
                                             const float* __restrict__ fb) {
    int blk = blockIdx.x;
    int chunk = blk % 73;
    int og = (blk / 73) % 8;
    int b  = blk / (73 * 8);
    __shared__ float ws[CH2][16];
    for (int i = threadIdx.x; i < CH2*16; i += 256) {
        int o = i % 16, ci = i / 16;
        ws[ci][o] = fw[(size_t)(og*16 + o)*CH2 + ci];
    }
    __syncthreads();
    int p = chunk * 256 + threadIdx.x;
    if (p >= HW2) return;
    const float* xb = g_frb2 + (size_t)b*CH2*HW2 + p;
    float acc[16];
    #pragma unroll
    for (int o = 0; o < 16; o++) acc[o] = fb[og*16 + o];
    for (int ci = 0; ci < CH2; ci++) {
        float v = xb[(size_t)ci*HW2];
        const float4* wp = (const float4*)&ws[ci][0];
        #pragma unroll
        for (int q = 0; q < 4; q++) {
            float4 w4 = wp[q];
            acc[q*4+0] += v * w4.x;
            acc[q*4+1] += v * w4.y;
            acc[q*4+2] += v * w4.z;
            acc[q*4+3] += v * w4.w;
        }
    }
    #pragma unroll
    for (int o = 0; o < 16; o++) {
        float a = acc[o];
        float gl = 0.5f * a * (1.0f + erff(a * 0.70710678118654752f));
        g_fd[((size_t)b*CH2 + og*16 + o)*HW2 + p] = gl;
    }
}

// ---------------- inverse H-dim FFT, even/odd DIT split ----------------
__global__ void k_invh() {
    int blk = blockIdx.x;
    int kg = blk % 13;
    int c  = (blk / 13) % CC;
    int b  = blk / (13 * CC);
    int k0 = kg * 8;
    int t = threadIdx.x; // 0..191
    int isO = (t >= 96);
    int u = isO ? t - 96 : t;
    float re[8], im[8];
    #pragma unroll
    for (int kk = 0; kk < 8; kk++) { re[kk] = 0.f; im[kk] = 0.f; }
    const float* fR = g_fd + (size_t)(b*CH2 + 2*c)*HW2;
    const float* fI = g_fd + (size_t)(b*CH2 + 2*c + 1)*HW2;
    __shared__ float2 stage[32*8];
    for (int mc = 0; mc < 6; mc++) {
        for (int i = threadIdx.x; i < 32*8; i += 192) {
            int mm = mc*32 + i/8, kk = i % 8;
            float2 v = make_float2(0.f, 0.f);
            if (k0 + kk < NW2) {
                v.x = fR[mm*NW2 + k0 + kk];
                v.y = fI[mm*NW2 + k0 + kk];
            }
            stage[i] = v;
        }
        __syncthreads();
        for (int mi = isO ? 1 : 0; mi < 32; mi += 2) {
            int mm = mc*32 + mi;
            int trow = isO ? (mm - 1) : mm;
            float tc = g_tabc[trow*HH + u], ts = g_tabs[trow*HH + u];
            #pragma unroll
            for (int kk = 0; kk < 8; kk++) {
                float2 f = stage[mi*8 + kk];
                re[kk] += f.x*tc + f.y*ts;   // e^{+i theta}; table holds e^{-i}
                im[kk] += f.y*tc - f.x*ts;
            }
        }
        __syncthreads();
    }
    __shared__ float2 AB[192][8];
    #pragma unroll
    for (int kk = 0; kk < 8; kk++) AB[t][kk] = make_float2(re[kk], im[kk]);
    __syncthreads();
    // X_u = A_u + v^u B_u ; X_{u+96} = A_u - v^u B_u ; v^u = (tabc, -tabs)
    float wc = g_tabc[HH + u], wsn = g_tabs[HH + u];
    float sgn = isO ? -1.f : 1.f;
    int h = t;
    for (int kk = 0; kk < 8; kk++) {
        int k = k0 + kk;
        if (k >= NW2) break;
        float2 A = AB[u][kk], Bv = AB[96 + u][kk];
        float brx = Bv.x*wc + Bv.y*wsn;
        float bry = Bv.y*wc - Bv.x*wsn;
        size_t o = (((size_t)(b*CC + c)*HH + h)*NW2 + k)*2;
        g_gh[o]   = A.x + sgn*brx;
        g_gh[o+1] = A.y + sgn*bry;
    }
}

// ---------------- irfft over W + xc branch + final ----------------
__global__ void k_final(const float* __restrict__ xcw, const float* __restrict__ xcb,
                        const float* __restrict__ bn2g, const float* __restrict__ bn2b,
                        float* __restrict__ out) {
    int blk = blockIdx.x;
    int hg = blk % 24;
    int c  = (blk / 24) % CC;
    int b  = blk / (24 * CC);
    int h0 = hg * 8;
    __shared__ float ghr[8][NW2];
    __shared__ float ghi[8][NW2];
    __shared__ float xws[CC];
    for (int i = threadIdx.x; i < 8*NW2; i += 192) {
        int r = i / NW2, k = i % NW2;
        size_t o = (((size_t)(b*CC + c)*HH + h0 + r)*NW2 + k)*2;
        ghr[r][k] = g_gh[o];
        ghi[r][k] = g_gh[o+1];
    }
    if (threadIdx.x < CC) xws[threadIdx.x] = xcw[c*CC + threadIdx.x];
    __syncthreads();
    int w = threadIdx.x;
    float acc[8];
    #pragma unroll
    for (int r = 0; r < 8; r++) acc[r] = 0.f;
    for (int k = 1; k < 96; k++) {
        float tc = g_tabc[k*HH + w], ts = g_tabs[k*HH + w];
        #pragma unroll
        for (int r = 0; r < 8; r++)
            acc[r] += ghr[r][k]*tc + ghi[r][k]*ts;
    }
    float xacc[8];
    #pragma unroll
    for (int r = 0; r < 8; r++) xacc[r] = 0.f;
    const float* x2b = g_x2 + (size_t)b*CC*HWP + (size_t)h0*WWD + w;
    for (int c2 = 0; c2 < CC; c2++) {
        float wv = xws[c2];
        const float* xp = x2b + (size_t)c2*HWP;
        #pragma unroll
        for (int r = 0; r < 8; r++) xacc[r] += wv * xp[r*WWD];
    }
    float par = (w & 1) ? -1.0f : 1.0f;
    float xb2 = xcb[c];
    float gg = BNINV * bn2g[c], bbq = bn2b[c];
    #pragma unroll
    for (int r = 0; r < 8; r++) {
        float of = (ghr[r][0] + ghr[r][96]*par + 2.0f*acc[r]) * (1.0f/192.0f);
        float xa = (xacc[r] + xb2) * gg + bbq;
        out[((size_t)b*CC + c)*HWP + (size_t)(h0 + r)*WWD + w] = fmaxf(xa, 0.0f) + of;
    }
}

// ---------------- launch ----------------
extern "C" void kernel_launch(void* const* d_in, const int* in_sizes, int n_in,
                              void* d_out, int out_size) {
    const float* x    = (const float*)d_in[0];
    const float* cdw  = (const float*)d_in[1];
    const float* lng  = (const float*)d_in[2];
    const float* lnb  = (const float*)d_in[3];
    const float* qw   = (const float*)d_in[4];
    const float* kw   = (const float*)d_in[5];
    const float* vw   = (const float*)d_in[6];
    const float* spw  = (const float*)d_in[7];
    const float* lw   = (const float*)d_in[8];
    const float* lb   = (const float*)d_in[9];
    const float* bng  = (const float*)d_in[10];
    const float* bnb  = (const float*)d_in[11];
    const float* fpew = (const float*)d_in[12];
    const float* fpeb = (const float*)d_in[13];
    const float* fdcw = (const float*)d_in[16];
    const float* fdcb = (const float*)d_in[17];
    const float* xcw  = (const float*)d_in[18];
    const float* xcb  = (const float*)d_in[19];
    const float* bn2g = (const float*)d_in[20];
    const float* bn2b = (const float*)d_in[21];
    float* out = (float*)d_out;

    k_tab<<<144, 256>>>();
    k_cdsum<<<16, 256>>>(cdw);
    k_contrast<<<BB*4*144, 256>>>(x, cdw);
    k_centinit<<<144, 256>>>(x);
    k_dist<<<288, 256>>>(x);
    k_asum<<<3, 128>>>();
    k_centupd<<<144, 256>>>(x);
    k_dist<<<288, 256>>>(x);
    k_asum<<<3, 128>>>();
    k_lnorm<<<288, 256>>>(x, lng, lnb);
    k_stoken<<<72, 256>>>();
    k_stokmm<<<72, 256>>>(spw);
    k_qkv<<<BB*12*144, 256>>>(qw, kw, vw);
    k_lepe<<<BB*CC*144, 256>>>(lw, lb);
    k_sattn<<<BB*NHD*(NSS/STILE), 256>>>();
    k_xattn<<<BB*NHD*144, 256>>>(x);
    k_fftw<<<BB*CC*24, 128>>>();
    k_ffth<<<BB*CC*13, 192>>>(bng, bnb);
    k_fpe<<<(BB*CH2*HW2 + 255)/256, 256>>>(fpew, fpeb);
    k_fdc<<<BB*8*73, 256>>>(fdcw, fdcb);
    k_invh<<<BB*CC*13, 192>>>();
    k_final<<<BB*CC*24, 192>>>(xcw, xcb, bn2g, bn2b, out);
}

// round 6
// speedup vs baseline: 1.5335x; 1.0319x over previous
#include <cuda_runtime.h>
#include <math.h>

#define BB 2
#define CC 64
#define HH 192
#define WWD 192
#define HWP 36864
#define NHD 4
#define DDIM 16
#define NSS 144
#define NHSS 12
#define SHH 16
#define NW2 97
#define HW2 18624
#define CH2 128
#define THETA 0.7f
#define ATTNSCALE 0.25f
#define BNINV 0.9999950000374997f

// ---------------- scratch ----------------
static __device__ float g_tabc[HH*HH];
static __device__ float g_tabs[HH*HH];
static __device__ float g_cdsum[CC*CC];
static __device__ float g_contrast[BB*CC*HWP];
static __device__ float g_cent[BB*2*CC*NSS];
static __device__ float g_asum[BB*NSS];
static __device__ float g_aff[BB*9*HWP];
static __device__ float g_xn[BB*CC*HWP];     // after k_xattn: reused as xc-relu output
static __device__ float g_q[BB*CC*HWP];
static __device__ float g_k[BB*CC*HWP];
static __device__ float g_v[BB*CC*HWP];
static __device__ float g_lepe[BB*CC*HWP];
static __device__ float g_stoken[BB*NSS*CC];
static __device__ float g_stok[BB*CC*NSS];
static __device__ float g_sout[BB*CC*NSS];
static __device__ float g_x2[BB*CC*HWP];
static __device__ float g_fw[BB*CC*HH*NW2*2];
static __device__ float g_frb[BB*CH2*HW2];
static __device__ float g_frb2[BB*CH2*HW2];
static __device__ float g_fd[BB*CH2*HW2];
static __device__ float g_gh[BB*CC*HH*NW2*2];

// ---------------- twiddle table ----------------
__global__ void k_tab() {
    int t = blockIdx.x * blockDim.x + threadIdx.x;
    if (t >= HH*HH) return;
    int i = t / HH, j = t % HH;
    int r = (i * j) % HH;
    float s, c;
    sincospif(-(float)r / 96.0f, &s, &c);
    g_tabc[t] = c;
    g_tabs[t] = s;
}

__global__ void k_cdsum(const float* __restrict__ cdw) {
    int t = blockIdx.x * blockDim.x + threadIdx.x;
    if (t >= CC*CC) return;
    float s = 0.f;
    #pragma unroll
    for (int k = 0; k < 9; k++) s += cdw[t*9 + k];
    g_cdsum[t] = s;
}

// ---------------- contrast: 16 output channels per block ----------------
__global__ void __launch_bounds__(256) k_contrast(const float* __restrict__ x,
                                                  const float* __restrict__ cdw) {
    int blk = blockIdx.x;
    int chunk = blk % 144;
    int og = (blk / 144) % 4;
    int b  = blk / (144 * 4);
    __shared__ float ws[CC][10][16];
    for (int i = threadIdx.x; i < CC*10*16; i += 256) {
        int o = i % 16;
        int tap = (i / 16) % 10;
        int ci = i / 160;
        int oo = og*16 + o;
        ws[ci][tap][o] = (tap < 9) ? cdw[((size_t)oo*CC + ci)*9 + tap]
                                   : -THETA * g_cdsum[oo*CC + ci];
    }
    __syncthreads();
    int p = chunk * 256 + threadIdx.x;
    int h = p / WWD, w = p % WWD;
    float acc[16];
    #pragma unroll
    for (int o = 0; o < 16; o++) acc[o] = 0.f;
    const float* xb = x + (size_t)b * CC * HWP;
    for (int ci = 0; ci < CC; ci++) {
        const float* xc = xb + (size_t)ci * HWP;
        float xv[10];
        #pragma unroll
        for (int ky = 0; ky < 3; ky++) {
            int hh = h + ky - 1;
            #pragma unroll
            for (int kx = 0; kx < 3; kx++) {
                int ww = w + kx - 1;
                xv[ky*3+kx] = ((unsigned)hh < HH && (unsigned)ww < WWD) ? xc[hh*WWD + ww] : 0.f;
            }
        }
        xv[9] = xv[4];
        #pragma unroll
        for (int tap = 0; tap < 10; tap++) {
            float v = xv[tap];
            const float4* wp = (const float4*)&ws[ci][tap][0];
            #pragma unroll
            for (int q = 0; q < 4; q++) {
                float4 w4 = wp[q];
                acc[q*4+0] += v * w4.x;
                acc[q*4+1] += v * w4.y;
                acc[q*4+2] += v * w4.z;
                acc[q*4+3] += v * w4.w;
            }
        }
    }
    #pragma unroll
    for (int o = 0; o < 16; o++)
        g_contrast[((size_t)b*CC + og*16 + o)*HWP + p] = acc[o];
}

// ---------------- cent init ----------------
__global__ void k_centinit(const float* __restrict__ x) {
    int t = blockIdx.x * 256 + threadIdx.x;
    if (t >= BB*2*CC*NSS) return;
    int s  = t % NSS;
    int ch = (t / NSS) % (2*CC);
    int b  = t / (NSS * 2 * CC);
    const float* src = (ch < CC) ? (x + ((size_t)b*CC + ch)*HWP)
                                 : (g_contrast + ((size_t)b*CC + (ch-CC))*HWP);
    int r0 = s / NHSS, c0 = s % NHSS;
    float acc = 0.f;
    for (int i = 0; i < SHH; i++) {
        const float* row = src + (r0*SHH + i)*WWD + c0*SHH;
        #pragma unroll
        for (int j = 0; j < SHH; j++) acc += row[j];
    }
    g_cent[t] = acc * (1.0f/256.0f);
}

// ---------------- distances + softmax -> aff ----------------
__global__ void k_dist(const float* __restrict__ x) {
    int t = blockIdx.x * 256 + threadIdx.x;
    if (t >= BB*HWP) return;
    int p = t % HWP, b = t / HWP;
    int h = p / WWD, w = p % WWD;
    int r = h / SHH, c = w / SHH;
    float d[9];
    int   cs[9];
    int   val[9];
    #pragma unroll
    for (int j = 0; j < 9; j++) {
        int dy = j/3 - 1, dx = j%3 - 1;
        int rr = r + dy, cc2 = c + dx;
        val[j] = (rr >= 0 && rr < NHSS && cc2 >= 0 && cc2 < NHSS);
        cs[j]  = val[j] ? rr*NHSS + cc2 : 0;
        d[j]   = 0.f;
    }
    const float* cb = g_cent + (size_t)b * 2 * CC * NSS;
    for (int ch = 0; ch < 2*CC; ch++) {
        float pix = (ch < CC) ? x[((size_t)b*CC + ch)*HWP + p]
                              : g_contrast[((size_t)b*CC + ch - CC)*HWP + p];
        float wgt = (ch < CC) ? 1.0f : 10.0f;
        const float* cr = cb + (size_t)ch * NSS;
        #pragma unroll
        for (int j = 0; j < 9; j++) {
            float df = pix - cr[cs[j]];
            d[j] += wgt * df * df;
        }
    }
    float m = 3.0e38f;
    #pragma unroll
    for (int j = 0; j < 9; j++) if (val[j] && d[j] < m) m = d[j];
    float e[9], sum = 0.f;
    #pragma unroll
    for (int j = 0; j < 9; j++) {
        e[j] = val[j] ? __expf(m - d[j]) : 0.f;
        sum += e[j];
    }
    float inv = 1.0f / sum;
    #pragma unroll
    for (int j = 0; j < 9; j++)
        g_aff[((size_t)b*9 + j)*HWP + p] = e[j] * inv;
}

// ---------------- asum ----------------
__global__ void k_asum() {
    int t = blockIdx.x * 128 + threadIdx.x;
    if (t >= BB*NSS) return;
    int s = t % NSS, b = t / NSS;
    int r0 = s / NHSS, c0 = s % NHSS;
    float acc = 0.f;
    for (int dy = -1; dy <= 1; dy++) {
        int r = r0 - dy;
        if ((unsigned)r >= NHSS) continue;
        for (int dx = -1; dx <= 1; dx++) {
            int c = c0 - dx;
            if ((unsigned)c >= NHSS) continue;
            int j = (dy+1)*3 + (dx+1);
            const float* ab = g_aff + ((size_t)b*9 + j)*HWP;
            for (int i = 0; i < SHH; i++) {
                const float* row = ab + (r*SHH + i)*WWD + c*SHH;
                #pragma unroll
                for (int jj = 0; jj < SHH; jj++) acc += row[jj];
            }
        }
    }
    g_asum[t] = acc;
}

// ---------------- cent update ----------------
__global__ void k_centupd(const float* __restrict__ x) {
    int t = blockIdx.x * 256 + threadIdx.x;
    if (t >= BB*2*CC*NSS) return;
    int s  = t % NSS;
    int ch = (t / NSS) % (2*CC);
    int b  = t / (NSS * 2 * CC);
    const float* src = (ch < CC) ? (x + ((size_t)b*CC + ch)*HWP)
                                 : (g_contrast + ((size_t)b*CC + (ch-CC))*HWP);
    int r0 = s / NHSS, c0 = s % NHSS;
    float acc = 0.f;
    for (int dy = -1; dy <= 1; dy++) {
        int r = r0 - dy;
        if ((unsigned)r >= NHSS) continue;
        for (int dx = -1; dx <= 1; dx++) {
            int c = c0 - dx;
            if ((unsigned)c >= NHSS) continue;
            int j = (dy+1)*3 + (dx+1);
            const float* ab = g_aff + ((size_t)b*9 + j)*HWP;
            for (int i = 0; i < SHH; i++) {
                int base = (r*SHH + i)*WWD + c*SHH;
                #pragma unroll
                for (int jj = 0; jj < SHH; jj++)
                    acc += ab[base + jj] * src[base + jj];
            }
        }
    }
    g_cent[t] = acc / (g_asum[(size_t)b*NSS + s] + 1e-16f);
}

// ---------------- LayerNorm ----------------
__global__ void k_lnorm(const float* __restrict__ x, const float* __restrict__ g,
                        const float* __restrict__ bta) {
    int t = blockIdx.x * 256 + threadIdx.x;
    if (t >= BB*HWP) return;
    int p = t % HWP, b = t / HWP;
    const float* xb = x + (size_t)b*CC*HWP + p;
    float sum = 0.f, sq = 0.f;
    for (int ch = 0; ch < CC; ch++) {
        float v = xb[(size_t)ch*HWP];
        sum += v; sq += v*v;
    }
    float mu = sum * (1.0f/CC);
    float var = sq * (1.0f/CC) - mu*mu;
    float rstd = rsqrtf(var + 1e-6f);
    float* ob = g_xn + (size_t)b*CC*HWP + p;
    for (int ch = 0; ch < CC; ch++) {
        float v = xb[(size_t)ch*HWP];
        ob[(size_t)ch*HWP] = (v - mu) * rstd * g[ch] + bta[ch];
    }
}

// ---------------- stoken gather ----------------
__global__ void k_stoken() {
    int t = blockIdx.x * 256 + threadIdx.x;
    if (t >= BB*NSS*CC) return;
    int ch = t % CC;
    int s  = (t / CC) % NSS;
    int b  = t / (CC * NSS);
    const float* src = g_xn + ((size_t)b*CC + ch)*HWP;
    int r0 = s / NHSS, c0 = s % NHSS;
    float acc = 0.f;
    for (int dy = -1; dy <= 1; dy++) {
        int r = r0 - dy;
        if ((unsigned)r >= NHSS) continue;
        for (int dx = -1; dx <= 1; dx++) {
            int c = c0 - dx;
            if ((unsigned)c >= NHSS) continue;
            int j = (dy+1)*3 + (dx+1);
            const float* ab = g_aff + ((size_t)b*9 + j)*HWP;
            for (int i = 0; i < SHH; i++) {
                int base = (r*SHH + i)*WWD + c*SHH;
                #pragma unroll
                for (int jj = 0; jj < SHH; jj++)
                    acc += ab[base + jj] * src[base + jj];
            }
        }
    }
    g_stoken[((size_t)b*NSS + s)*CC + ch] = acc / (g_asum[(size_t)b*NSS + s] + 1e-16f);
}

// ---------------- stok = stoken @ sp_w^T ----------------
__global__ void k_stokmm(const float* __restrict__ spw) {
    int t = blockIdx.x * 256 + threadIdx.x;
    if (t >= BB*CC*NSS) return;
    int s = t % NSS;
    int o = (t / NSS) % CC;
    int b = t / (NSS * CC);
    const float* st = g_stoken + ((size_t)b*NSS + s)*CC;
    const float* w  = spw + o*CC;
    float acc = 0.f;
    #pragma unroll 8
    for (int c = 0; c < CC; c++) acc += w[c] * st[c];
    g_stok[((size_t)b*CC + o)*NSS + s] = acc;
}

// ---------------- q/k/v: 32 outputs per block ----------------
__global__ void __launch_bounds__(256) k_qkv(const float* __restrict__ qw,
                                             const float* __restrict__ kw,
                                             const float* __restrict__ vw) {
    int blk = blockIdx.x;
    int chunk = blk % 144;
    int og = (blk / 144) % 6;
    int b  = blk / (144 * 6);
    __shared__ float ws[CC][32];
    for (int i = threadIdx.x; i < CC*32; i += 256) {
        int o = i % 32, ci = i / 32;
        int oo = og*32 + o;
        const float* wsrc = (oo < 64) ? (qw + oo*CC)
                          : (oo < 128 ? kw + (oo-64)*CC : vw + (oo-128)*CC);
        ws[ci][o] = wsrc[ci];
    }
    __syncthreads();
    int p = chunk * 256 + threadIdx.x;
    const float* xb = g_xn + (size_t)b*CC*HWP + p;
    float acc[32];
    #pragma unroll
    for (int o = 0; o < 32; o++) acc[o] = 0.f;
    for (int ci = 0; ci < CC; ci++) {
        float v = xb[(size_t)ci*HWP];
        const float4* wp = (const float4*)&ws[ci][0];
        #pragma unroll
        for (int q = 0; q < 8; q++) {
            float4 w4 = wp[q];
            acc[q*4+0] += v * w4.x;
            acc[q*4+1] += v * w4.y;
            acc[q*4+2] += v * w4.z;
            acc[q*4+3] += v * w4.w;
        }
    }
    #pragma unroll
    for (int o = 0; o < 32; o++) {
        int oo = og*32 + o;
        float* dst = (oo < 64) ? (g_q + ((size_t)b*64 + oo)*HWP)
                   : (oo < 128 ? (g_k + ((size_t)b*64 + oo-64)*HWP)
                               : (g_v + ((size_t)b*64 + oo-128)*HWP));
        dst[p] = acc[o];
    }
}

// ---------------- lepe: coalesced Tflat write (thread = 16 channels of one pixel) ----------------
__global__ void __launch_bounds__(256) k_lepe(const float* __restrict__ lw,
                                              const float* __restrict__ lb) {
    __shared__ float ws[CC*9];
    __shared__ float bs[CC];
    for (int i = threadIdx.x; i < CC*9; i += 256) ws[i] = lw[i];
    if (threadIdx.x < CC) bs[threadIdx.x] = lb[threadIdx.x];
    __syncthreads();
    int blk = blockIdx.x;
    int pblk = blk % 576;
    int b = blk / 576;
    int cg = threadIdx.x & 3;
    int pl = threadIdx.x >> 2;
    int p = pblk * 64 + pl;
    int h = p / WWD, w = p % WWD;
    int off[9];
    bool vld[9];
    #pragma unroll
    for (int tap = 0; tap < 9; tap++) {
        int ky = tap/3 - 1, kx = tap%3 - 1;
        int hh = h + ky, ww = w + kx;
        vld[tap] = ((unsigned)hh < HH) && ((unsigned)ww < WWD);
        off[tap] = hh*WWD + ww;
    }
    const float* vb = g_v + (size_t)b*CC*HWP;
    float o[16];
    #pragma unroll
    for (int j = 0; j < 16; j++) {
        int c = cg*16 + j;
        const float* vc = vb + (size_t)c*HWP;
        float acc = bs[c];
        #pragma unroll
        for (int tap = 0; tap < 9; tap++)
            if (vld[tap]) acc += vc[off[tap]] * ws[c*9 + tap];
        o[j] = acc;
    }
    float4* dst = (float4*)(g_lepe + (size_t)b*CC*HWP + (size_t)p*CC + cg*16);
    #pragma unroll
    for (int q = 0; q < 4; q++)
        dst[q] = make_float4(o[q*4], o[q*4+1], o[q*4+2], o[q*4+3]);
}

// ---------------- s_attn: no-max softmax, STILE=8 ----------------
#define STILE 8
__global__ void __launch_bounds__(256) k_sattn() {
    int blk = blockIdx.x;
    int sg = blk % (NSS/STILE);
    int hh = (blk / (NSS/STILE)) % NHD;
    int b  = blk / ((NSS/STILE) * NHD);
    int s0 = sg * STILE;
    int tid = threadIdx.x;
    __shared__ float stks[STILE][DDIM];
    if (tid < STILE*DDIM) {
        int si = tid / DDIM, d = tid % DDIM;
        stks[si][d] = g_stok[((size_t)(b*NHD + hh)*DDIM + d)*NSS + s0 + si];
    }
    __syncthreads();
    float l[STILE], acc[STILE][DDIM];
    #pragma unroll
    for (int si = 0; si < STILE; si++) {
        l[si] = 0.f;
        #pragma unroll
        for (int d = 0; d < DDIM; d++) acc[si][d] = 0.f;
    }
    const float* kb = g_k + (size_t)(b*NHD + hh)*DDIM*HWP;
    const float* vb = g_v + (size_t)(b*NHD + hh)*DDIM*HWP;
    for (int p = tid; p < HWP; p += 256) {
        float kd[DDIM], vd[DDIM];
        #pragma unroll
        for (int d = 0; d < DDIM; d++) kd[d] = kb[(size_t)d*HWP + p];
        #pragma unroll
        for (int d = 0; d < DDIM; d++) vd[d] = vb[(size_t)d*HWP + p];
        #pragma unroll
        for (int si = 0; si < STILE; si++) {
            float lg = 0.f;
            #pragma unroll
            for (int d = 0; d < DDIM; d++) lg += kd[d] * stks[si][d];
            float e = __expf(lg * ATTNSCALE);
            l[si] += e;
            #pragma unroll
            for (int d = 0; d < DDIM; d++) acc[si][d] += e * vd[d];
        }
    }
    __shared__ float rl[256], ra[DDIM*256];
    for (int si = 0; si < STILE; si++) {
        rl[tid] = l[si];
        #pragma unroll
        for (int d = 0; d < DDIM; d++) ra[d*256 + tid] = acc[si][d];
        __syncthreads();
        for (int str = 128; str > 0; str >>= 1) {
            if (tid < str) {
                rl[tid] += rl[tid + str];
                #pragma unroll
                for (int d = 0; d < DDIM; d++)
                    ra[d*256 + tid] += ra[d*256 + tid + str];
            }
            __syncthreads();
        }
        if (tid < DDIM)
            g_sout[((size_t)(b*NHD + hh)*DDIM + tid)*NSS + s0 + si] = ra[tid*256] / rl[0];
        __syncthreads();
    }
}

// ---------------- x_attn single-pass + x2 = x + x_out + lepe ----------------
__global__ void __launch_bounds__(256) k_xattn(const float* __restrict__ x) {
    int blk = blockIdx.x;
    int chunk = blk % 144;
    int hh = (blk / 144) % NHD;
    int b  = blk / (144 * NHD);
    int tid = threadIdx.x;
    __shared__ float st[DDIM*NSS];
    __shared__ float so[DDIM*NSS];
    size_t base = (size_t)(b*NHD + hh)*DDIM*NSS;
    for (int i = tid; i < DDIM*NSS; i += 256) {
        st[i] = g_stok[base + i];
        so[i] = g_sout[base + i];
    }
    __syncthreads();
    int p = chunk * 256 + tid;
    float qd[DDIM];
    #pragma unroll
    for (int d = 0; d < DDIM; d++)
        qd[d] = g_q[((size_t)(b*NHD + hh)*DDIM + d)*HWP + p];
    float l = 0.f;
    float acc[DDIM];
    #pragma unroll
    for (int d = 0; d < DDIM; d++) acc[d] = 0.f;
    for (int s = 0; s < NSS; s++) {
        float lg = 0.f;
        #pragma unroll
        for (int d = 0; d < DDIM; d++) lg += qd[d] * st[d*NSS + s];
        float e = __expf(lg * ATTNSCALE);
        l += e;
        #pragma unroll
        for (int d = 0; d < DDIM; d++) acc[d] += e * so[d*NSS + s];
    }
    float invl = 1.0f / l;
    #pragma unroll
    for (int d = 0; d < DDIM; d++) {
        int cch = hh*DDIM + d;
        size_t o = ((size_t)b*CC + cch)*HWP + p;
        g_x2[o] = x[o] + acc[d]*invl + g_lepe[o];
    }
}

// ---------------- xc branch: 32 outputs per block, relu'd into g_xn ----------------
__global__ void __launch_bounds__(256) k_xc(const float* __restrict__ xcw,
                                            const float* __restrict__ xcb,
                                            const float* __restrict__ bn2g,
                                            const float* __restrict__ bn2b) {
    int blk = blockIdx.x;
    int chunk = blk % 144;
    int og = (blk / 144) % 2;
    int b  = blk / (144 * 2);
    __shared__ float ws[CC][32];
    for (int i = threadIdx.x; i < CC*32; i += 256) {
        int o = i % 32, ci = i / 32;
        ws[ci][o] = xcw[(size_t)(og*32 + o)*CC + ci];
    }
    __syncthreads();
    int p = chunk * 256 + threadIdx.x;
    const float* xb = g_x2 + (size_t)b*CC*HWP + p;
    float acc[32];
    #pragma unroll
    for (int o = 0; o < 32; o++) acc[o] = 0.f;
    for (int ci = 0; ci < CC; ci++) {
        float v = xb[(size_t)ci*HWP];
        const float4* wp = (const float4*)&ws[ci][0];
        #pragma unroll
        for (int q = 0; q < 8; q++) {
            float4 w4 = wp[q];
            acc[q*4+0] += v * w4.x;
            acc[q*4+1] += v * w4.y;
            acc[q*4+2] += v * w4.z;
            acc[q*4+3] += v * w4.w;
        }
    }
    #pragma unroll
    for (int o = 0; o < 32; o++) {
        int oo = og*32 + o;
        float xa = (acc[o] + xcb[oo]) * (BNINV * bn2g[oo]) + bn2b[oo];
        g_xn[((size_t)b*CC + oo)*HWP + p] = fmaxf(xa, 0.0f);
    }
}

// ---------------- W-dim rfft, 16 rows per block ----------------
__global__ void k_fftw() {
    int blk = blockIdx.x;
    int hg = blk % 12;
    int c  = (blk / 12) % CC;
    int b  = blk / (12 * CC);
    int h0 = hg * 16;
    __shared__ float rows[16][WWD];
    for (int i = threadIdx.x; i < 16*WWD; i += 128)
        rows[i/WWD][i%WWD] = g_x2[((size_t)b*CC + c)*HWP + (size_t)(h0 + i/WWD)*WWD + i%WWD];
    __syncthreads();
    int k = threadIdx.x;
    if (k >= NW2) return;
    float re[16], im[16];
    #pragma unroll
    for (int r = 0; r < 16; r++) { re[r] = 0.f; im[r] = 0.f; }
    for (int w = 0; w < WWD; w++) {
        float tc = g_tabc[w*HH + k], ts = g_tabs[w*HH + k];
        #pragma unroll
        for (int r = 0; r < 16; r++) {
            float v = rows[r][w];
            re[r] += v * tc;
            im[r] += v * ts;
        }
    }
    #pragma unroll
    for (int r = 0; r < 16; r++) {
        size_t o = (((size_t)(b*CC + c)*HH + h0 + r)*NW2 + k)*2;
        g_fw[o] = re[r]; g_fw[o+1] = im[r];
    }
}

// ---------------- H-dim FFT, even/odd DIT split + BN -> frb ----------------
__global__ void k_ffth(const float* __restrict__ bng, const float* __restrict__ bnb) {
    int blk = blockIdx.x;
    int kg = blk % 13;
    int c  = (blk / 13) % CC;
    int b  = blk / (13 * CC);
    int k0 = kg * 8;
    int t = threadIdx.x; // 0..191
    int isO = (t >= 96);
    int u = isO ? t - 96 : t;
    float re[8], im[8];
    #pragma unroll
    for (int kk = 0; kk < 8; kk++) { re[kk] = 0.f; im[kk] = 0.f; }
    __shared__ float2 stage[32*8];
    for (int hc = 0; hc < 6; hc++) {
        for (int i = threadIdx.x; i < 32*8; i += 192) {
            int hh2 = hc*32 + i/8, kk = i % 8;
            float2 v = make_float2(0.f, 0.f);
            if (k0 + kk < NW2) {
                size_t o = (((size_t)(b*CC + c)*HH + hh2)*NW2 + k0 + kk)*2;
                v.x = g_fw[o]; v.y = g_fw[o+1];
            }
            stage[i] = v;
        }
        __syncthreads();
        for (int hi = isO ? 1 : 0; hi < 32; hi += 2) {
            int h = hc*32 + hi;
            int trow = isO ? (h - 1) : h;
            float tc = g_tabc[trow*HH + u], ts = g_tabs[trow*HH + u];
            #pragma unroll
            for (int kk = 0; kk < 8; kk++) {
                float2 f = stage[hi*8 + kk];
                re[kk] += f.x*tc - f.y*ts;
                im[kk] += f.x*ts + f.y*tc;
            }
        }
        __syncthreads();
    }
    __shared__ float2 EO[192][8];
    #pragma unroll
    for (int kk = 0; kk < 8; kk++) EO[t][kk] = make_float2(re[kk], im[kk]);
    __syncthreads();
    float wc = g_tabc[HH + u], wsn = g_tabs[HH + u];
    float sgn = isO ? -1.f : 1.f;
    const float sc = 1.0f / 192.0f;
    int chR = 2*c, chI = 2*c + 1;
    float gr = BNINV * bng[chR], br = bnb[chR];
    float gi = BNINV * bng[chI], bi = bnb[chI];
    int m = t;
    for (int kk = 0; kk < 8; kk++) {
        int k = k0 + kk;
        if (k >= NW2) break;
        float2 E = EO[u][kk], O = EO[96 + u][kk];
        float orx = O.x*wc - O.y*wsn;
        float ory = O.x*wsn + O.y*wc;
        float Xr = E.x + sgn*orx;
        float Xi = E.y + sgn*ory;
        g_frb[((size_t)(b*CH2 + chR)*HH + m)*NW2 + k] = Xr*sc*gr + br;
        g_frb[((size_t)(b*CH2 + chI)*HH + m)*NW2 + k] = Xi*sc*gi + bi;
    }
}

// ---------------- fpe: depthwise 3x3 + residual ----------------
__global__ void k_fpe(const float* __restrict__ fw, const float* __restrict__ fb) {
    int t = blockIdx.x * 256 + threadIdx.x;
    if (t >= BB*CH2*HW2) return;
    int k  = t % NW2;
    int m  = (t / NW2) % HH;
    int ch = (t / HW2) % CH2;
    const float* base = g_frb + (size_t)(t / HW2) * HW2;
    float acc = fb[ch];
    #pragma unroll
    for (int ky = -1; ky <= 1; ky++) {
        int mm = m + ky;
        if ((unsigned)mm >= HH) continue;
        #pragma unroll
        for (int kx = -1; kx <= 1; kx++) {
            int kk2 = k + kx;
            if ((unsigned)kk2 >= NW2) continue;
            acc += base[mm*NW2 + kk2] * fw[ch*9 + (ky+1)*3 + (kx+1)];
        }
    }
    g_frb2[t] = acc + base[m*NW2 + k];
}

// ---------------- fdc: 32 outputs per block + GELU ----------------
__global__ void __launch_bounds__(256) k_fdc(const float* __restrict__ fw,
                                             const float* __restrict__ fb) {
    int blk = blockIdx.x;
    int chunk = blk % 73;
    int og = (blk / 73) % 4;
    int b  = blk / (73 * 4);
    __shared__ float ws[CH2][32];
    for (int i = threadIdx.x; i < CH2*32; i += 256) {
        int o = i % 32, ci = i / 32;
        ws[ci][o] = fw[(size_t)(og*32 + o)*CH2 + ci];
    }
    __syncthreads();
    int p = chunk * 256 + threadIdx.x;
    if (p >= HW2) return;
    const float* xb = g_frb2 + (size_t)b*CH2*HW2 + p;
    float acc[32];
    #pragma unroll
    for (int o = 0; o < 32; o++) acc[o] = fb[og*32 + o];
    for (int ci = 0; ci < CH2; ci++) {
        float v = xb[(size_t)ci*HW2];
        const float4* wp = (const float4*)&ws[ci][0];
        #pragma unroll
        for (int q = 0; q < 8; q++) {
            float4 w4 = wp[q];
            acc[q*4+0] += v * w4.x;
            acc[q*4+1] += v * w4.y;
            acc[q*4+2] += v * w4.z;
            acc[q*4+3] += v * w4.w;
        }
    }
    #pragma unroll
    for (int o = 0; o < 32; o++) {
        float a = acc[o];
        float gl = 0.5f * a * (1.0f + erff(a * 0.70710678118654752f));
        g_fd[((size_t)b*CH2 + og*32 + o)*HW2 + p] = gl;
    }
}

// ---------------- inverse H-dim FFT, even/odd DIT split ----------------
__global__ void k_invh() {
    int blk = blockIdx.x;
    int kg = blk % 13;
    int c  = (blk / 13) % CC;
    int b  = blk / (13 * CC);
    int k0 = kg * 8;
    int t = threadIdx.x;
    int isO = (t >= 96);
    int u = isO ? t - 96 : t;
    float re[8], im[8];
    #pragma unroll
    for (int kk = 0; kk < 8; kk++) { re[kk] = 0.f; im[kk] = 0.f; }
    const float* fR = g_fd + (size_t)(b*CH2 + 2*c)*HW2;
    const float* fI = g_fd + (size_t)(b*CH2 + 2*c + 1)*HW2;
    __shared__ float2 stage[32*8];
    for (int mc = 0; mc < 6; mc++) {
        for (int i = threadIdx.x; i < 32*8; i += 192) {
            int mm = mc*32 + i/8, kk = i % 8;
            float2 v = make_float2(0.f, 0.f);
            if (k0 + kk < NW2) {
                v.x = fR[mm*NW2 + k0 + kk];
                v.y = fI[mm*NW2 + k0 + kk];
            }
            stage[i] = v;
        }
        __syncthreads();
        for (int mi = isO ? 1 : 0; mi < 32; mi += 2) {
            int mm = mc*32 + mi;
            int trow = isO ? (mm - 1) : mm;
            float tc = g_tabc[trow*HH + u], ts = g_tabs[trow*HH + u];
            #pragma unroll
            for (int kk = 0; kk < 8; kk++) {
                float2 f = stage[mi*8 + kk];
                re[kk] += f.x*tc + f.y*ts;
                im[kk] += f.y*tc - f.x*ts;
            }
        }
        __syncthreads();
    }
    __shared__ float2 AB[192][8];
    #pragma unroll
    for (int kk = 0; kk < 8; kk++) AB[t][kk] = make_float2(re[kk], im[kk]);
    __syncthreads();
    float wc = g_tabc[HH + u], wsn = g_tabs[HH + u];
    float sgn = isO ? -1.f : 1.f;
    int h = t;
    for (int kk = 0; kk < 8; kk++) {
        int k = k0 + kk;
        if (k >= NW2) break;
        float2 A = AB[u][kk], Bv = AB[96 + u][kk];
        float brx = Bv.x*wc + Bv.y*wsn;
        float bry = Bv.y*wc - Bv.x*wsn;
        size_t o = (((size_t)(b*CC + c)*HH + h)*NW2 + k)*2;
        g_gh[o]   = A.x + sgn*brx;
        g_gh[o+1] = A.y + sgn*bry;
    }
}

// ---------------- irfft over W + add xc (precomputed) ----------------
__global__ void k_final(float* __restrict__ out) {
    int blk = blockIdx.x;
    int hg = blk % 24;
    int c  = (blk / 24) % CC;
    int b  = blk / (24 * CC);
    int h0 = hg * 8;
    __shared__ float ghr[8][NW2];
    __shared__ float ghi[8][NW2];
    for (int i = threadIdx.x; i < 8*NW2; i += 192) {
        int r = i / NW2, k = i % NW2;
        size_t o = (((size_t)(b*CC + c)*HH + h0 + r)*NW2 + k)*2;
        ghr[r][k] = g_gh[o];
        ghi[r][k] = g_gh[o+1];
    }
    __syncthreads();
    int w = threadIdx.x;
    float acc[8];
    #pragma unroll
    for (int r = 0; r < 8; r++) acc[r] = 0.f;
    for (int k = 1; k < 96; k++) {
        float tc = g_tabc[k*HH + w], ts = g_tabs[k*HH + w];
        #pragma unroll
        for (int r = 0; r < 8; r++)
            acc[r] += ghr[r][k]*tc + ghi[r][k]*ts;
    }
    float par = (w & 1) ? -1.0f : 1.0f;
    const float* xcb2 = g_xn + ((size_t)b*CC + c)*HWP + (size_t)h0*WWD + w;
    #pragma unroll
    for (int r = 0; r < 8; r++) {
        float of = (ghr[r][0] + ghr[r][96]*par + 2.0f*acc[r]) * (1.0f/192.0f);
        out[((size_t)b*CC + c)*HWP + (size_t)(h0 + r)*WWD + w] = xcb2[r*WWD] + of;
    }
}

// ---------------- launch ----------------
extern "C" void kernel_launch(void* const* d_in, const int* in_sizes, int n_in,
                              void* d_out, int out_size) {
    const float* x    = (const float*)d_in[0];
    const float* cdw  = (const float*)d_in[1];
    const float* lng  = (const float*)d_in[2];
    const float* lnb  = (const float*)d_in[3];
    const float* qw   = (const float*)d_in[4];
    const float* kw   = (const float*)d_in[5];
    const float* vw   = (const float*)d_in[6];
    const float* spw  = (const float*)d_in[7];
    const float* lw   = (const float*)d_in[8];
    const float* lb   = (const float*)d_in[9];
    const float* bng  = (const float*)d_in[10];
    const float* bnb  = (const float*)d_in[11];
    const float* fpew = (const float*)d_in[12];
    const float* fpeb = (const float*)d_in[13];
    const float* fdcw = (const float*)d_in[16];
    const float* fdcb = (const float*)d_in[17];
    const float* xcw  = (const float*)d_in[18];
    const float* xcb  = (const float*)d_in[19];
    const float* bn2g = (const float*)d_in[20];
    const float* bn2b = (const float*)d_in[21];
    float* out = (float*)d_out;

    k_tab<<<144, 256>>>();
    k_cdsum<<<16, 256>>>(cdw);
    k_contrast<<<BB*4*144, 256>>>(x, cdw);
    k_centinit<<<144, 256>>>(x);
    k_dist<<<288, 256>>>(x);
    k_asum<<<3, 128>>>();
    k_centupd<<<144, 256>>>(x);
    k_dist<<<288, 256>>>(x);
    k_asum<<<3, 128>>>();
    k_lnorm<<<288, 256>>>(x, lng, lnb);
    k_stoken<<<72, 256>>>();
    k_stokmm<<<72, 256>>>(spw);
    k_qkv<<<BB*6*144, 256>>>(qw, kw, vw);
    k_lepe<<<BB*576, 256>>>(lw, lb);
    k_sattn<<<BB*NHD*(NSS/STILE), 256>>>();
    k_xattn<<<BB*NHD*144, 256>>>(x);
    k_xc<<<BB*2*144, 256>>>(xcw, xcb, bn2g, bn2b);
    k_fftw<<<BB*CC*12, 128>>>();
    k_ffth<<<BB*CC*13, 192>>>(bng, bnb);
    k_fpe<<<(BB*CH2*HW2 + 255)/256, 256>>>(fpew, fpeb);
    k_fdc<<<BB*4*73, 256>>>(fdcw, fdcb);
    k_invh<<<BB*CC*13, 192>>>();
    k_final<<<BB*CC*24, 192>>>(out);
}